// round 13
// baseline (speedup 1.0000x reference)
#include <cuda_runtime.h>
#include <cuda_fp16.h>
#include <cstdint>

// Problem constants
#define BATCH 2
#define CH    256
#define NPIX  4096
#define MIPC  8
#define CQD   32
#define CN    (CH*NPIX)
#define ESPLIT 8

// ===================== static scratch ==================================
__device__ float  g_pool[BATCH*CH*128];
__device__ float  g_yca [BATCH*MIPC*128];
__device__ float  g_ah  [BATCH*CH*64];
__device__ float  g_aw  [BATCH*CH*64];
__device__ __half g_r   [BATCH*CN];              // NHWC half
__device__ __half g_t1  [BATCH*CN];
__device__ __half g_t2  [BATCH*CN];
__device__ __half g_cat [(long)BATCH*NPIX*1024];
__device__ __half g_yc  [(long)BATCH*NPIX*512];
__device__ __half g_res16[BATCH*CN];             // NHWC half (operand)
__device__ float  g_res32[BATCH*CN];             // NHWC f32 (residual)
__device__ __half g_resT16[BATCH*CN];            // NCHW half (e GEMM)
__device__ float  g_resT32[BATCH*CN];            // NCHW f32 (final residual)
__device__ __half g_qk  [BATCH*NPIX*64];
__device__ __half g_v   [BATCH*CN];              // NCHW half
__device__ __half g_attn[(long)BATCH*NPIX*NPIX]; // 64 MB half
__device__ float  g_pam [BATCH*CN];              // NCHW f32
__device__ float  g_epart[BATCH*ESPLIT*CH*CH];
__device__ __half g_ac  [BATCH*CH*CH];
// folded weights (half) + biases (f32)
__device__ float  g_w1f[MIPC*CH];   __device__ float g_b1f[MIPC];
__device__ __half g_ws1[CH*CH];     __device__ float g_bs1[CH];
__device__ __half g_ws2[CH*CH];     __device__ float g_bs2[CH];
__device__ __half g_ws3[CH*2304];   __device__ float g_bs3[CH];
__device__ __half g_ws4[CH*CH];     __device__ float g_bs4[CH];
__device__ __half g_ws5[CH*1024];   __device__ float g_bs5[CH];
__device__ __half g_ws6[CH*2304];   __device__ float g_bs6[CH];
__device__ __half g_ws7[CH*512];    __device__ float g_bs7[CH];
__device__ __half g_wqk[64*CH];     __device__ float g_bqk[64];
__device__ __half g_wpv[CH*CH];

// ===================== merged fold/convert (1 launch) ==================
struct FoldArgs {
    const float* w[8]; const float* bn[8]; const float* bin[8];
    __half* wf[8]; float* bf[8];
    int O[8]; int Ke[8]; int ro[8];
    float* w1f_f;
    const float *pq_w, *pq_b, *pk_w, *pk_b, *pv_w;
    __half *qkw, *pvw;
    float *qkb;
};

__global__ void fold_all_k(FoldArgs a)
{
    int j = blockIdx.y, o = blockIdx.x;
    if (j == 8) {
        if (o >= 64) return;
        const float* src = (o < 32) ? (a.pq_w + (long)o*256)
                                    : (a.pk_w + (long)(o-32)*256);
        for (int k = threadIdx.x; k < 256; k += blockDim.x)
            a.qkw[(long)o*256 + k] = __float2half(src[k]);
        if (threadIdx.x == 0)
            a.qkb[o] = (o < 32) ? a.pq_b[o] : a.pk_b[o-32];
        return;
    }
    if (j == 9) {
        for (int k = threadIdx.x; k < 256; k += blockDim.x)
            a.pvw[(long)o*256 + k] = __float2half(a.pv_w[(long)o*256 + k]);
        return;
    }
    int O = a.O[j];
    if (o >= O) return;
    const float* bn = a.bn[j];
    float g  = bn[o], be = bn[O+o], mn = bn[2*O+o], vr = bn[3*O+o];
    float s = g * rsqrtf(vr + 1e-5f);
    int Ke = a.Ke[j];
    const float* w = a.w[j];
    if (j == 0) {
        for (int k = threadIdx.x; k < Ke; k += blockDim.x)
            a.w1f_f[(long)o*Ke + k] = w[(long)o*Ke + k] * s;
    } else if (a.ro[j]) {
        __half* wf = a.wf[j];
        for (int k = threadIdx.x; k < Ke; k += blockDim.x) {
            int t = k >> 8, ci = k & 255;
            wf[(long)o*Ke + k] = __float2half(w[((long)o*256 + ci)*9 + t] * s);
        }
    } else {
        __half* wf = a.wf[j];
        for (int k = threadIdx.x; k < Ke; k += blockDim.x)
            wf[(long)o*Ke + k] = __float2half(w[(long)o*Ke + k] * s);
    }
    if (threadIdx.x == 0)
        a.bf[j][o] = (a.bin[j] ? a.bin[j][o] : 0.f) * s + be - mn * s;
}

// ===================== fp16 mma.sync primitives ========================
__device__ __forceinline__ void mma_f16(float c[4], const uint32_t a[4],
                                        const uint32_t b[2]) {
    asm volatile(
        "mma.sync.aligned.m16n8k16.row.col.f32.f16.f16.f32 "
        "{%0,%1,%2,%3}, {%4,%5,%6,%7}, {%8,%9}, {%0,%1,%2,%3};"
        : "+f"(c[0]), "+f"(c[1]), "+f"(c[2]), "+f"(c[3])
        : "r"(a[0]), "r"(a[1]), "r"(a[2]), "r"(a[3]), "r"(b[0]), "r"(b[1]));
}
__device__ __forceinline__ void ldsm4(uint32_t& r0, uint32_t& r1,
                                      uint32_t& r2, uint32_t& r3, uint32_t addr) {
    asm volatile("ldmatrix.sync.aligned.m8n8.x4.shared.b16 {%0,%1,%2,%3}, [%4];"
                 : "=r"(r0), "=r"(r1), "=r"(r2), "=r"(r3) : "r"(addr));
}
__device__ __forceinline__ void cp16(uint32_t dst, const void* src, int srcsize) {
    asm volatile("cp.async.cg.shared.global [%0], [%1], 16, %2;"
                 :: "r"(dst), "l"(src), "r"(srcsize));
}
#define CP_COMMIT() asm volatile("cp.async.commit_group;" ::: "memory")
#define CP_WAIT2()  asm volatile("cp.async.wait_group 2;" ::: "memory")

// SMEM rows: 32 halves data + 8 halves pad = 20 words
// Block tile 64(M) x 128(N): A stage 64 rows, B stage 128 rows
#define ROWW 20
#define ASTG (64*ROWW)           // 1280 words
#define BSTG (128*ROWW)          // 2560 words
#define STGW (ASTG+BSTG)         // 3840 words per stage
#define NSTG 4
#define SMEM_WORDS (NSTG*STGW)   // 15360 words = 61440 B

template<typename OutT>
__device__ __forceinline__ void st2(OutT* p, float v0, float v1);
template<> __device__ __forceinline__ void st2<__half>(__half* p, float v0, float v1) {
    *(__half2*)p = __floats2half2_rn(v0, v1);
}
template<> __device__ __forceinline__ void st2<float>(float* p, float v0, float v1) {
    *(float2*)p = make_float2(v0, v1);
}

// D[m0..+63][n0..+127] = act( sum_k A[m][k]*B[n][k] + bias )  (half in)
// ACT: 0 none, 1 SiLU (+opt f32 aux), 4 final combine
template<int ACT, bool CONV3, typename OutT>
__global__ __launch_bounds__(128) void mma_gemm(
    const __half* __restrict__ A, const __half* __restrict__ B,
    const float* __restrict__ bias, OutT* __restrict__ C,
    int K, int lda, int ldb, int ldc, int Bn, int ncols, int bias_on_m,
    long sA_, long sB_, long sC_,
    int nsplit = 1, float* __restrict__ Caux = nullptr,
    const float* __restrict__ f1 = nullptr, const float* __restrict__ f2 = nullptr,
    const float* __restrict__ gam1 = nullptr, const float* __restrict__ gam2 = nullptr)
{
    extern __shared__ uint32_t smu[];
    uint32_t sbase = (uint32_t)__cvta_generic_to_shared(smu);

    int bz = blockIdx.z;
    int batch = bz, slice = 0;
    if (nsplit > 1) { batch = bz / nsplit; slice = bz - batch * nsplit; }
    A += batch * sA_ + (long)slice * K;
    B += batch * sB_ + (long)slice * K;
    C += (long)bz * sC_;
    float gg1 = 0.f, gg2 = 0.f;
    if (ACT == 4) {
        f1 += (long)batch * CN; f2 += (long)batch * CN;
        gg1 = gam1[0]; gg2 = gam2[0];
    }

    int m0 = blockIdx.y * 64, n0 = blockIdx.x * 128;
    int tid = threadIdx.x;
    int lane = tid & 31, w = tid >> 5;
    int wm = w >> 1, wn = w & 1;           // 2x2 warp grid, 32x64 tiles
    int g = lane >> 2, t = lane & 3;

    float acc[2][8][4] = {};
    int lrow = tid >> 2, lv = tid & 3;
    int T = K >> 5;

    // ldmatrix lane address bases (bytes from sbase)
    uint32_t aAddr = sbase +
        (((wm*32 + (lane & 7) + ((lane >> 3) & 1)*8)*ROWW + ((lane >> 4) & 1)*4) << 2);
    uint32_t bAddr = sbase + (ASTG << 2) +
        (((wn*64 + (lane & 7) + ((lane >> 4) & 1)*8)*ROWW + ((lane >> 3) & 1)*4) << 2);

    auto issue = [&](int it) {
        int s = it % NSTG;
        int k0 = it * 32;
        uint32_t ab = sbase + (s*STGW)*4;
        uint32_t bb = ab + ASTG*4;
        if (!CONV3) {
            #pragma unroll
            for (int i = 0; i < 2; i++) {
                int m = i*32 + lrow;
                cp16(ab + ((m*ROWW + lv*4)*4),
                     A + (long)(m0+m)*lda + k0 + lv*8, 16);
            }
        } else {
            int tap = k0 >> 8, ci0 = k0 & 255;
            int dy = tap/3 - 1, dx = tap%3 - 1;
            #pragma unroll
            for (int i = 0; i < 2; i++) {
                int m = i*32 + lrow;
                int pix = m0 + m;
                int y = (pix >> 6) + dy, x = (pix & 63) + dx;
                bool ok = ((unsigned)y < 64u) && ((unsigned)x < 64u);
                const __half* src = ok ? (A + (long)((y<<6)+x)*lda + ci0 + lv*8) : A;
                cp16(ab + ((m*ROWW + lv*4)*4), src, ok ? 16 : 0);
            }
        }
        #pragma unroll
        for (int i = 0; i < 4; i++) {
            int n = i*32 + lrow;
            bool ok = (n0 + n) < Bn;
            const __half* src = ok ? (B + (long)(n0+n)*ldb + k0 + lv*8) : B;
            cp16(bb + ((n*ROWW + lv*4)*4), src, ok ? 16 : 0);
        }
        CP_COMMIT();
    };

    auto compute = [&](int s) {
        uint32_t soff = (uint32_t)(s*STGW) << 2;
        #pragma unroll
        for (int ks = 0; ks < 2; ks++) {
            uint32_t af[2][4], bf[8][2];
            #pragma unroll
            for (int mt = 0; mt < 2; mt++)
                ldsm4(af[mt][0], af[mt][1], af[mt][2], af[mt][3],
                      aAddr + soff + ((mt*16*ROWW + ks*8) << 2));
            #pragma unroll
            for (int p = 0; p < 4; p++) {
                uint32_t r0, r1, r2, r3;
                ldsm4(r0, r1, r2, r3,
                      bAddr + soff + ((p*16*ROWW + ks*8) << 2));
                bf[2*p][0]   = r0; bf[2*p][1]   = r1;
                bf[2*p+1][0] = r2; bf[2*p+1][1] = r3;
            }
            #pragma unroll
            for (int mt = 0; mt < 2; mt++)
                #pragma unroll
                for (int nt = 0; nt < 8; nt++)
                    mma_f16(acc[mt][nt], af[mt], bf[nt]);
        }
    };

    // prologue: 3 committed groups (empty groups pad when T small)
    issue(0);
    if (T > 1) issue(1); else CP_COMMIT();
    if (T > 2) issue(2); else CP_COMMIT();

    for (int it = 0; it < T; it++) {
        CP_WAIT2();            // stage `it` landed
        __syncthreads();       // all warps done with slot being overwritten
        if (it + 3 < T) issue(it + 3); else CP_COMMIT();
        compute(it % NSTG);
    }

    // epilogue
    int valid = ncols - n0; if (valid > 128) valid = 128;
    #pragma unroll
    for (int mt = 0; mt < 2; mt++) {
        #pragma unroll
        for (int half_ = 0; half_ < 2; half_++) {
            int m = m0 + wm*32 + mt*16 + g + half_*8;
            float bm = (bias && bias_on_m) ? bias[m] : 0.f;
            long base = (long)m*ldc + n0;
            #pragma unroll
            for (int nt = 0; nt < 8; nt++) {
                int nl = wn*64 + nt*8 + 2*t;
                if (nl >= valid) continue;
                float v0 = acc[mt][nt][half_*2 + 0] + bm;
                float v1 = acc[mt][nt][half_*2 + 1] + bm;
                if (bias && !bias_on_m) { v0 += bias[n0+nl]; v1 += bias[n0+nl+1]; }
                if (ACT == 1) {
                    v0 = v0 / (1.f + __expf(-v0));
                    v1 = v1 / (1.f + __expf(-v1));
                    if (Caux) *(float2*)(Caux + (long)bz*sC_ + base + nl)
                              = make_float2(v0, v1);
                } else if (ACT == 4) {
                    float2 r1 = *(const float2*)(f1 + base + nl);
                    float2 r2 = *(const float2*)(f2 + base + nl);
                    v0 = 3.f*r1.x + gg1*r2.x + gg2*v0;
                    v1 = 3.f*r1.y + gg1*r2.y + gg2*v1;
                }
                st2<OutT>(C + base + nl, v0, v1);
            }
        }
    }
}

// ===================== small FMA GEMM (CoordAtt yca only) =============
__global__ __launch_bounds__(256) void gemm_small_hsw(
    const float* __restrict__ A, const float* __restrict__ B,
    const float* __restrict__ bias, float* __restrict__ C,
    int M, int N, int K, int ldb, long sB, long sC)
{
    int b = blockIdx.z;
    B += (long)b*sB; C += (long)b*sC;
    int m0 = blockIdx.y*64, n0 = blockIdx.x*64;
    __shared__ float As[16][64], Bs[16][65];
    int tid = threadIdx.x, tx = tid & 15, ty = tid >> 4;
    float acc[4][4] = {};
    for (int k0 = 0; k0 < K; k0 += 16) {
        int i = tid >> 2, jb = (tid & 3)*4, mI = m0 + i;
        #pragma unroll
        for (int j = 0; j < 4; j++) {
            int k = k0 + jb + j;
            As[jb+j][i] = (mI < M && k < K) ? A[(long)mI*K + k] : 0.f;
        }
        int jr = tid >> 4, nb = (tid & 15)*4, k = k0 + jr;
        #pragma unroll
        for (int n = 0; n < 4; n++) {
            int nn = n0 + nb + n;
            Bs[jr][nb+n] = (k < K && nn < N) ? B[(long)k*ldb + nn] : 0.f;
        }
        __syncthreads();
        #pragma unroll
        for (int j = 0; j < 16; j++) {
            float a[4], bb[4];
            #pragma unroll
            for (int i2 = 0; i2 < 4; i2++) a[i2]  = As[j][ty*4+i2];
            #pragma unroll
            for (int i2 = 0; i2 < 4; i2++) bb[i2] = Bs[j][tx*4+i2];
            #pragma unroll
            for (int i2 = 0; i2 < 4; i2++)
                #pragma unroll
                for (int jj = 0; jj < 4; jj++) acc[i2][jj] += a[i2]*bb[jj];
        }
        __syncthreads();
    }
    #pragma unroll
    for (int i = 0; i < 4; i++) {
        int mI = m0 + ty*4 + i;
        if (mI >= M) continue;
        float bv = bias ? bias[mI] : 0.f;
        #pragma unroll
        for (int jj = 0; jj < 4; jj++) {
            int n = n0 + tx*4 + jj;
            if (n >= N) continue;
            float v = acc[i][jj] + bv;
            float tq = fminf(fmaxf(v+3.f,0.f),6.f); v = v*tq*(1.f/6.f);  // h-swish
            C[(long)mI*N + n] = v;
        }
    }
}

// ===================== CoordAtt glue ==================================
__global__ void ca_pool_k(const float* __restrict__ x, float* __restrict__ pool)
{
    int c = blockIdx.x, b = blockIdx.y, t = threadIdx.x;
    const float* p = x + ((long)b*CH + c)*NPIX;
    float sh = 0.f, sw = 0.f;
    for (int i = 0; i < 64; i++) sh += p[t*64 + i];
    for (int i = 0; i < 64; i++) sw += p[i*64 + t];
    float* o = pool + ((long)b*CH + c)*128;
    o[t] = sh*(1.f/64.f); o[64+t] = sw*(1.f/64.f);
}

__global__ void ca_proj_k(const float* __restrict__ wh, const float* __restrict__ bh,
                          const float* __restrict__ ww, const float* __restrict__ bw)
{
    int hw = blockIdx.y, b = blockIdx.z;
    int idx = blockIdx.x*256 + threadIdx.x;
    int c = idx >> 6, pos = idx & 63;
    const float* W  = hw ? ww : wh;
    const float* Bi = hw ? bw : bh;
    const float* y  = g_yca + (long)b*MIPC*128 + (hw ? 64 : 0) + pos;
    float s = Bi[c];
    #pragma unroll
    for (int i = 0; i < MIPC; i++) s += W[c*MIPC + i] * y[i*128];
    float o = 1.f / (1.f + __expf(-s));
    float* dst = hw ? g_aw : g_ah;
    dst[((long)b*CH + c)*64 + pos] = o;
}

__global__ void ca_apply_k(const float* __restrict__ x)
{
    long i = blockIdx.x*256L + threadIdx.x;
    if (i >= (long)BATCH*CN) return;
    int c = (int)(i & 255); long t = i >> 8;
    int pix = (int)(t & 4095); int b = (int)(t >> 12);
    long bc = (long)b*CH + c;
    int y = pix >> 6, xx = pix & 63;
    g_r[i] = __float2half(
        x[(long)b*CN + (long)c*NPIX + pix] * g_aw[bc*64+xx] * g_ah[bc*64+y]);
}

// ============ fused maxpool 5/9/13 (one plane per block) ===============
__global__ __launch_bounds__(256) void mp_all_k(__half* __restrict__ cat)
{
    __shared__ __half2 p0[4096], p1[4096];
    int c2 = blockIdx.x, b = blockIdx.y;
    __half2* base = (__half2*)(cat + (long)b*NPIX*1024);
    int tid = threadIdx.x;
    #pragma unroll
    for (int i = tid; i < 4096; i += 256) p0[i] = base[(long)i*512 + c2];
    __syncthreads();
    #pragma unroll
    for (int pass = 1; pass <= 3; pass++) {
        #pragma unroll 4
        for (int i = tid; i < 4096; i += 256) {
            int x = i & 63;
            __half2 m = p0[i];
            if (x >= 1)  m = __hmax2(m, p0[i-1]);
            if (x >= 2)  m = __hmax2(m, p0[i-2]);
            if (x <= 62) m = __hmax2(m, p0[i+1]);
            if (x <= 61) m = __hmax2(m, p0[i+2]);
            p1[i] = m;
        }
        __syncthreads();
        #pragma unroll 4
        for (int i = tid; i < 4096; i += 256) {
            int y = i >> 6;
            __half2 m = p1[i];
            if (y >= 1)  m = __hmax2(m, p1[i-64]);
            if (y >= 2)  m = __hmax2(m, p1[i-128]);
            if (y <= 62) m = __hmax2(m, p1[i+64]);
            if (y <= 61) m = __hmax2(m, p1[i+128]);
            p0[i] = m;
            base[(long)i*512 + pass*128 + c2] = m;
        }
        __syncthreads();
    }
}

// ===================== PAM softmax (half rows of 4096) =================
__global__ void softmax_row_k(__half* __restrict__ a)
{
    __half2* p = (__half2*)(a + (long)blockIdx.x * 4096);
    int t = threadIdx.x;
    __shared__ float red[256];
    float2 v[8];
    #pragma unroll
    for (int i = 0; i < 8; i++) v[i] = __half22float2(p[t + i*256]);
    float mx = v[0].x;
    #pragma unroll
    for (int i = 0; i < 8; i++) { mx = fmaxf(mx, v[i].x); mx = fmaxf(mx, v[i].y); }
    red[t] = mx; __syncthreads();
    for (int s = 128; s > 0; s >>= 1) { if (t < s) red[t] = fmaxf(red[t], red[t+s]); __syncthreads(); }
    mx = red[0]; __syncthreads();
    float sum = 0.f;
    #pragma unroll
    for (int i = 0; i < 8; i++) {
        v[i].x = __expf(v[i].x - mx); v[i].y = __expf(v[i].y - mx);
        sum += v[i].x + v[i].y;
    }
    red[t] = sum; __syncthreads();
    for (int s = 128; s > 0; s >>= 1) { if (t < s) red[t] += red[t+s]; __syncthreads(); }
    float inv = 1.f / red[0];
    #pragma unroll
    for (int i = 0; i < 8; i++)
        p[t + i*256] = __floats2half2_rn(v[i].x * inv, v[i].y * inv);
}

// ====== CAM softmax fused with split-K reduce ==========================
__global__ void cam_softmax_k(const float* __restrict__ ep, __half* __restrict__ ac)
{
    long row = blockIdx.x;           // b*256 + c
    int b = (int)(row >> 8); int r = (int)(row & 255);
    int t = threadIdx.x;
    float v = 0.f;
    #pragma unroll
    for (int k = 0; k < ESPLIT; k++)
        v += ep[((long)(b*ESPLIT + k) << 16) + r*256 + t];
    __shared__ float sm[256];
    sm[t] = v; __syncthreads();
    for (int s = 128; s > 0; s >>= 1) { if (t < s) sm[t] = fmaxf(sm[t], sm[t+s]); __syncthreads(); }
    float rowmax = sm[0]; __syncthreads();
    float z = rowmax - v;
    sm[t] = z; __syncthreads();
    for (int s = 128; s > 0; s >>= 1) { if (t < s) sm[t] = fmaxf(sm[t], sm[t+s]); __syncthreads(); }
    float zm = sm[0]; __syncthreads();
    float pe = __expf(z - zm);
    sm[t] = pe; __syncthreads();
    for (int s = 128; s > 0; s >>= 1) { if (t < s) sm[t] += sm[t+s]; __syncthreads(); }
    ac[row*256 + t] = __float2half(pe / sm[0]);
}

// ============ tiled transpose NHWC(f32) -> NCHW f32 + half =============
__global__ void transpose_k(const float* __restrict__ src)
{
    __shared__ float s[32][33];
    int b = blockIdx.z;
    int p0 = blockIdx.x*32, c0 = blockIdx.y*32;
    int tx = threadIdx.x, ty = threadIdx.y;  // 32 x 8
    const float* S = src + (long)b*CN;
    float*  D32 = g_resT32 + (long)b*CN;
    __half* D16 = g_resT16 + (long)b*CN;
    #pragma unroll
    for (int j = 0; j < 32; j += 8)
        s[ty+j][tx] = S[(long)(p0+ty+j)*256 + c0+tx];
    __syncthreads();
    #pragma unroll
    for (int j = 0; j < 32; j += 8) {
        float v = s[tx][ty+j];
        long o = (long)(c0+ty+j)*4096 + p0+tx;
        D32[o] = v;
        D16[o] = __float2half(v);
    }
}

// ======================================================================
extern "C" void kernel_launch(void* const* d_in, const int* in_sizes, int n_in,
                              void* d_out, int out_size)
{
    const float* x     = (const float*)d_in[0];
    const float* ca_w1 = (const float*)d_in[1];
    const float* ca_b1 = (const float*)d_in[2];
    const float* ca_bn = (const float*)d_in[3];
    const float* ca_wh = (const float*)d_in[4];
    const float* ca_bh = (const float*)d_in[5];
    const float* ca_ww = (const float*)d_in[6];
    const float* ca_bw = (const float*)d_in[7];
    const float* s1_w  = (const float*)d_in[8];  const float* s1_bn = (const float*)d_in[9];
    const float* s2_w  = (const float*)d_in[10]; const float* s2_bn = (const float*)d_in[11];
    const float* s3_w  = (const float*)d_in[12]; const float* s3_bn = (const float*)d_in[13];
    const float* s4_w  = (const float*)d_in[14]; const float* s4_bn = (const float*)d_in[15];
    const float* s5_w  = (const float*)d_in[16]; const float* s5_bn = (const float*)d_in[17];
    const float* s6_w  = (const float*)d_in[18]; const float* s6_bn = (const float*)d_in[19];
    const float* s7_w  = (const float*)d_in[20]; const float* s7_bn = (const float*)d_in[21];
    const float* pq_w  = (const float*)d_in[22]; const float* pq_b  = (const float*)d_in[23];
    const float* pk_w  = (const float*)d_in[24]; const float* pk_b  = (const float*)d_in[25];
    const float* pv_w  = (const float*)d_in[26]; const float* pv_b  = (const float*)d_in[27];
    const float* gpa   = (const float*)d_in[28];
    const float* gca   = (const float*)d_in[29];

    float *pool,*yca,*res32,*pam,*epart,*w1f,*b1f,*bs1,*bs2,*bs3,*bs4,*bs5,*bs6,*bs7,*bqk;
    __half *r16,*t1,*t2,*cat,*yc,*res16,*resT16,*qk,*vb,*attn,*ac;
    __half *ws1,*ws2,*ws3,*ws4,*ws5,*ws6,*ws7,*wqk,*wpv;
    float *resT32;
    cudaGetSymbolAddress((void**)&pool, g_pool);    cudaGetSymbolAddress((void**)&yca, g_yca);
    cudaGetSymbolAddress((void**)&r16, g_r);        cudaGetSymbolAddress((void**)&t1, g_t1);
    cudaGetSymbolAddress((void**)&t2, g_t2);        cudaGetSymbolAddress((void**)&cat, g_cat);
    cudaGetSymbolAddress((void**)&yc, g_yc);
    cudaGetSymbolAddress((void**)&res16, g_res16);  cudaGetSymbolAddress((void**)&res32, g_res32);
    cudaGetSymbolAddress((void**)&resT16, g_resT16);cudaGetSymbolAddress((void**)&resT32, g_resT32);
    cudaGetSymbolAddress((void**)&qk, g_qk);        cudaGetSymbolAddress((void**)&vb, g_v);
    cudaGetSymbolAddress((void**)&attn, g_attn);    cudaGetSymbolAddress((void**)&pam, g_pam);
    cudaGetSymbolAddress((void**)&epart, g_epart);  cudaGetSymbolAddress((void**)&ac, g_ac);
    cudaGetSymbolAddress((void**)&w1f, g_w1f);      cudaGetSymbolAddress((void**)&b1f, g_b1f);
    cudaGetSymbolAddress((void**)&ws1, g_ws1);      cudaGetSymbolAddress((void**)&bs1, g_bs1);
    cudaGetSymbolAddress((void**)&ws2, g_ws2);      cudaGetSymbolAddress((void**)&bs2, g_bs2);
    cudaGetSymbolAddress((void**)&ws3, g_ws3);      cudaGetSymbolAddress((void**)&bs3, g_bs3);
    cudaGetSymbolAddress((void**)&ws4, g_ws4);      cudaGetSymbolAddress((void**)&bs4, g_bs4);
    cudaGetSymbolAddress((void**)&ws5, g_ws5);      cudaGetSymbolAddress((void**)&bs5, g_bs5);
    cudaGetSymbolAddress((void**)&ws6, g_ws6);      cudaGetSymbolAddress((void**)&bs6, g_bs6);
    cudaGetSymbolAddress((void**)&ws7, g_ws7);      cudaGetSymbolAddress((void**)&bs7, g_bs7);
    cudaGetSymbolAddress((void**)&wqk, g_wqk);      cudaGetSymbolAddress((void**)&bqk, g_bqk);
    cudaGetSymbolAddress((void**)&wpv, g_wpv);

    const int SMEMSZ = SMEM_WORDS * 4;   // 61440 B
    cudaFuncSetAttribute(mma_gemm<0,false,__half>, cudaFuncAttributeMaxDynamicSharedMemorySize, SMEMSZ);
    cudaFuncSetAttribute(mma_gemm<0,false,float>,  cudaFuncAttributeMaxDynamicSharedMemorySize, SMEMSZ);
    cudaFuncSetAttribute(mma_gemm<1,false,__half>, cudaFuncAttributeMaxDynamicSharedMemorySize, SMEMSZ);
    cudaFuncSetAttribute(mma_gemm<1,true,__half>,  cudaFuncAttributeMaxDynamicSharedMemorySize, SMEMSZ);
    cudaFuncSetAttribute(mma_gemm<4,false,float>,  cudaFuncAttributeMaxDynamicSharedMemorySize, SMEMSZ);

    const int EB  = (BATCH*CN + 255)/256;

    // ---- merged fold/convert ----
    FoldArgs fa;
    fa.w[0]=ca_w1; fa.bn[0]=ca_bn; fa.bin[0]=ca_b1; fa.wf[0]=nullptr; fa.bf[0]=b1f; fa.O[0]=MIPC; fa.Ke[0]=256;  fa.ro[0]=0;
    fa.w[1]=s1_w;  fa.bn[1]=s1_bn; fa.bin[1]=nullptr; fa.wf[1]=ws1; fa.bf[1]=bs1; fa.O[1]=CH; fa.Ke[1]=256;  fa.ro[1]=0;
    fa.w[2]=s2_w;  fa.bn[2]=s2_bn; fa.bin[2]=nullptr; fa.wf[2]=ws2; fa.bf[2]=bs2; fa.O[2]=CH; fa.Ke[2]=256;  fa.ro[2]=0;
    fa.w[3]=s3_w;  fa.bn[3]=s3_bn; fa.bin[3]=nullptr; fa.wf[3]=ws3; fa.bf[3]=bs3; fa.O[3]=CH; fa.Ke[3]=2304; fa.ro[3]=1;
    fa.w[4]=s4_w;  fa.bn[4]=s4_bn; fa.bin[4]=nullptr; fa.wf[4]=ws4; fa.bf[4]=bs4; fa.O[4]=CH; fa.Ke[4]=256;  fa.ro[4]=0;
    fa.w[5]=s5_w;  fa.bn[5]=s5_bn; fa.bin[5]=nullptr; fa.wf[5]=ws5; fa.bf[5]=bs5; fa.O[5]=CH; fa.Ke[5]=1024; fa.ro[5]=0;
    fa.w[6]=s6_w;  fa.bn[6]=s6_bn; fa.bin[6]=nullptr; fa.wf[6]=ws6; fa.bf[6]=bs6; fa.O[6]=CH; fa.Ke[6]=2304; fa.ro[6]=1;
    fa.w[7]=s7_w;  fa.bn[7]=s7_bn; fa.bin[7]=nullptr; fa.wf[7]=ws7; fa.bf[7]=bs7; fa.O[7]=CH; fa.Ke[7]=512;  fa.ro[7]=0;
    fa.w1f_f=w1f;
    fa.pq_w=pq_w; fa.pq_b=pq_b; fa.pk_w=pk_w; fa.pk_b=pk_b; fa.pv_w=pv_w;
    fa.qkw=wqk; fa.qkb=bqk; fa.pvw=wpv;
    fold_all_k<<<dim3(256,10),256>>>(fa);

    // ---- CoordAtt ----
    ca_pool_k<<<dim3(CH,BATCH),64>>>(x, pool);
    gemm_small_hsw<<<dim3(2,1,BATCH),256>>>(w1f, pool, b1f, yca,
        MIPC,128,CH, 128, (long)CH*128, (long)MIPC*128);
    ca_proj_k<<<dim3(64,2,BATCH),256>>>(ca_wh, ca_bh, ca_ww, ca_bw);
    ca_apply_k<<<EB,256>>>(x);

    // ---- SPPCSPC ----
    mma_gemm<1,false,__half><<<dim3(2,64,BATCH),128,SMEMSZ>>>(r16, ws1, bs1, t1,
        256,256,256,256, 256,256,0, (long)CN,0,(long)CN);
    mma_gemm<1,true,__half><<<dim3(2,64,BATCH),128,SMEMSZ>>>(t1, ws3, bs3, t2,
        2304,256,2304,256, 256,256,0, (long)CN,0,(long)CN);
    mma_gemm<1,false,__half><<<dim3(2,64,BATCH),128,SMEMSZ>>>(t2, ws4, bs4, cat,
        256,256,256,1024, 256,256,0, (long)CN,0,(long)NPIX*1024);
    mp_all_k<<<dim3(128,BATCH),256>>>(cat);
    mma_gemm<1,false,__half><<<dim3(2,64,BATCH),128,SMEMSZ>>>(cat, ws5, bs5, t1,
        1024,1024,1024,256, 256,256,0, (long)NPIX*1024,0,(long)CN);
    mma_gemm<1,true,__half><<<dim3(2,64,BATCH),128,SMEMSZ>>>(t1, ws6, bs6, yc,
        2304,256,2304,512, 256,256,0, (long)CN,0,(long)NPIX*512);
    mma_gemm<1,false,__half><<<dim3(2,64,BATCH),128,SMEMSZ>>>(r16, ws2, bs2, yc+256,
        256,256,256,512, 256,256,0, (long)CN,0,(long)NPIX*512);
    mma_gemm<1,false,__half><<<dim3(2,64,BATCH),128,SMEMSZ>>>(yc, ws7, bs7, res16,
        512,512,512,256, 256,256,0, (long)NPIX*512,0,(long)CN, 1, res32);

    // ---- PAM ----
    mma_gemm<0,false,__half><<<dim3(1,64,BATCH),128,SMEMSZ>>>(res16, wqk, bqk, qk,
        256,256,256,64, 64,64,0, (long)CN,0,(long)NPIX*64);
    mma_gemm<0,false,__half><<<dim3(32,4,BATCH),128,SMEMSZ>>>(wpv, res16, pv_b, vb,
        256,256,256,NPIX, NPIX,NPIX,1, 0,(long)CN,(long)CN);
    mma_gemm<0,false,__half><<<dim3(32,64,BATCH),128,SMEMSZ>>>(qk, qk+32, nullptr, attn,
        CQD,64,64,NPIX, NPIX,NPIX,0, (long)NPIX*64,(long)NPIX*64,(long)NPIX*NPIX);
    softmax_row_k<<<BATCH*NPIX,256>>>(attn);
    mma_gemm<0,false,float><<<dim3(32,4,BATCH),128,SMEMSZ>>>(vb, attn, nullptr, pam,
        NPIX,NPIX,NPIX,NPIX, NPIX,NPIX,0, (long)CN,(long)NPIX*NPIX,(long)CN);

    // ---- CAM ----
    transpose_k<<<dim3(128,8,BATCH),dim3(32,8)>>>(res32);
    mma_gemm<0,false,float><<<dim3(2,4,BATCH*ESPLIT),128,SMEMSZ>>>(resT16, resT16, nullptr, epart,
        NPIX/ESPLIT,NPIX,NPIX,256, 256,256,0, (long)CN,(long)CN,(long)CH*CH, ESPLIT);
    cam_softmax_k<<<BATCH*CH,256>>>(epart, ac);
    mma_gemm<4,false,float><<<dim3(32,4,BATCH),128,SMEMSZ>>>(ac, res16, nullptr, (float*)d_out,
        256,256,256,NPIX, NPIX,NPIX,0, (long)CH*CH,(long)CN,(long)CN,
        1, nullptr, resT32, pam, gpa, gca);
}

// round 14
// speedup vs baseline: 1.0598x; 1.0598x over previous
#include <cuda_runtime.h>
#include <cuda_fp16.h>
#include <cstdint>

// Problem constants
#define BATCH 2
#define CH    256
#define NPIX  4096
#define MIPC  8
#define CQD   32
#define CN    (CH*NPIX)
#define ESPLIT 8

// ===================== static scratch ==================================
__device__ float  g_pool[BATCH*CH*128];
__device__ float  g_yca [BATCH*MIPC*128];
__device__ float  g_ah  [BATCH*CH*64];
__device__ float  g_aw  [BATCH*CH*64];
__device__ __half g_r   [BATCH*CN];              // NHWC half
__device__ __half g_t1  [BATCH*CN];
__device__ __half g_t2  [BATCH*CN];
__device__ __half g_cat [(long)BATCH*NPIX*1024];
__device__ __half g_yc  [(long)BATCH*NPIX*512];
__device__ __half g_res16[BATCH*CN];             // NHWC half (operand)
__device__ float  g_res32[BATCH*CN];             // NHWC f32 (residual)
__device__ __half g_resT16[BATCH*CN];            // NCHW half (e GEMM)
__device__ float  g_resT32[BATCH*CN];            // NCHW f32 (final residual)
__device__ __half g_qk  [BATCH*NPIX*64];
__device__ __half g_v   [BATCH*CN];              // NCHW half
__device__ __half g_attn[(long)BATCH*NPIX*NPIX]; // 64 MB half
__device__ float  g_pam [BATCH*CN];              // NCHW f32
__device__ float  g_epart[BATCH*ESPLIT*CH*CH];
__device__ __half g_ac  [BATCH*CH*CH];
// folded weights (half) + biases (f32)
__device__ float  g_w1f[MIPC*CH];   __device__ float g_b1f[MIPC];
__device__ __half g_ws1[CH*CH];     __device__ float g_bs1[CH];
__device__ __half g_ws2[CH*CH];     __device__ float g_bs2[CH];
__device__ __half g_ws3[CH*2304];   __device__ float g_bs3[CH];
__device__ __half g_ws4[CH*CH];     __device__ float g_bs4[CH];
__device__ __half g_ws5[CH*1024];   __device__ float g_bs5[CH];
__device__ __half g_ws6[CH*2304];   __device__ float g_bs6[CH];
__device__ __half g_ws7[CH*512];    __device__ float g_bs7[CH];
__device__ __half g_wqk[64*CH];     __device__ float g_bqk[64];
__device__ __half g_wpv[CH*CH];

// ===================== merged fold/convert (1 launch) ==================
struct FoldArgs {
    const float* w[8]; const float* bn[8]; const float* bin[8];
    __half* wf[8]; float* bf[8];
    int O[8]; int Ke[8]; int ro[8];
    float* w1f_f;
    const float *pq_w, *pq_b, *pk_w, *pk_b, *pv_w;
    __half *qkw, *pvw;
    float *qkb;
};

__global__ void fold_all_k(FoldArgs a)
{
    int j = blockIdx.y, o = blockIdx.x;
    if (j == 8) {
        if (o >= 64) return;
        const float* src = (o < 32) ? (a.pq_w + (long)o*256)
                                    : (a.pk_w + (long)(o-32)*256);
        for (int k = threadIdx.x; k < 256; k += blockDim.x)
            a.qkw[(long)o*256 + k] = __float2half(src[k]);
        if (threadIdx.x == 0)
            a.qkb[o] = (o < 32) ? a.pq_b[o] : a.pk_b[o-32];
        return;
    }
    if (j == 9) {
        for (int k = threadIdx.x; k < 256; k += blockDim.x)
            a.pvw[(long)o*256 + k] = __float2half(a.pv_w[(long)o*256 + k]);
        return;
    }
    int O = a.O[j];
    if (o >= O) return;
    const float* bn = a.bn[j];
    float g  = bn[o], be = bn[O+o], mn = bn[2*O+o], vr = bn[3*O+o];
    float s = g * rsqrtf(vr + 1e-5f);
    int Ke = a.Ke[j];
    const float* w = a.w[j];
    if (j == 0) {
        for (int k = threadIdx.x; k < Ke; k += blockDim.x)
            a.w1f_f[(long)o*Ke + k] = w[(long)o*Ke + k] * s;
    } else if (a.ro[j]) {
        __half* wf = a.wf[j];
        for (int k = threadIdx.x; k < Ke; k += blockDim.x) {
            int t = k >> 8, ci = k & 255;
            wf[(long)o*Ke + k] = __float2half(w[((long)o*256 + ci)*9 + t] * s);
        }
    } else {
        __half* wf = a.wf[j];
        for (int k = threadIdx.x; k < Ke; k += blockDim.x)
            wf[(long)o*Ke + k] = __float2half(w[(long)o*Ke + k] * s);
    }
    if (threadIdx.x == 0)
        a.bf[j][o] = (a.bin[j] ? a.bin[j][o] : 0.f) * s + be - mn * s;
}

// ===================== fp16 mma.sync primitives ========================
__device__ __forceinline__ void mma_f16(float c[4], const uint32_t a[4],
                                        const uint32_t b[2]) {
    asm volatile(
        "mma.sync.aligned.m16n8k16.row.col.f32.f16.f16.f32 "
        "{%0,%1,%2,%3}, {%4,%5,%6,%7}, {%8,%9}, {%0,%1,%2,%3};"
        : "+f"(c[0]), "+f"(c[1]), "+f"(c[2]), "+f"(c[3])
        : "r"(a[0]), "r"(a[1]), "r"(a[2]), "r"(a[3]), "r"(b[0]), "r"(b[1]));
}
__device__ __forceinline__ void ldsm4(uint32_t& r0, uint32_t& r1,
                                      uint32_t& r2, uint32_t& r3, uint32_t addr) {
    asm volatile("ldmatrix.sync.aligned.m8n8.x4.shared.b16 {%0,%1,%2,%3}, [%4];"
                 : "=r"(r0), "=r"(r1), "=r"(r2), "=r"(r3) : "r"(addr));
}
__device__ __forceinline__ void cp16(uint32_t dst, const void* src, int srcsize) {
    asm volatile("cp.async.cg.shared.global [%0], [%1], 16, %2;"
                 :: "r"(dst), "l"(src), "r"(srcsize));
}
#define CP_COMMIT() asm volatile("cp.async.commit_group;" ::: "memory")
#define CP_WAIT1()  asm volatile("cp.async.wait_group 1;" ::: "memory")

// SMEM rows: 32 halves data + 8 halves pad = 20 words
// Block tile 64(M) x 128(N): A stage 64 rows, B stage 128 rows
#define ROWW 20
#define ASTG (64*ROWW)           // 1280 words
#define BSTG (128*ROWW)          // 2560 words
#define STGW (ASTG+BSTG)         // 3840 words per stage
#define NSTG 3
#define SMEM_WORDS (NSTG*STGW)   // 11520 words = 46 KB

template<typename OutT>
__device__ __forceinline__ void st2(OutT* p, float v0, float v1);
template<> __device__ __forceinline__ void st2<__half>(__half* p, float v0, float v1) {
    *(__half2*)p = __floats2half2_rn(v0, v1);
}
template<> __device__ __forceinline__ void st2<float>(float* p, float v0, float v1) {
    *(float2*)p = make_float2(v0, v1);
}

// D[m0..+63][n0..+127] = act( sum_k A[m][k]*B[n][k] + bias )  (half in)
// ACT: 0 none, 1 SiLU (+opt f32 aux), 4 final combine
template<int ACT, bool CONV3, typename OutT>
__global__ __launch_bounds__(128) void mma_gemm(
    const __half* __restrict__ A, const __half* __restrict__ B,
    const float* __restrict__ bias, OutT* __restrict__ C,
    int K, int lda, int ldb, int ldc, int Bn, int ncols, int bias_on_m,
    long sA_, long sB_, long sC_,
    int nsplit = 1, float* __restrict__ Caux = nullptr,
    const float* __restrict__ f1 = nullptr, const float* __restrict__ f2 = nullptr,
    const float* __restrict__ gam1 = nullptr, const float* __restrict__ gam2 = nullptr)
{
    extern __shared__ uint32_t smu[];
    uint32_t sbase = (uint32_t)__cvta_generic_to_shared(smu);

    int bz = blockIdx.z;
    int batch = bz, slice = 0;
    if (nsplit > 1) { batch = bz / nsplit; slice = bz - batch * nsplit; }
    A += batch * sA_ + (long)slice * K;
    B += batch * sB_ + (long)slice * K;
    C += (long)bz * sC_;
    float gg1 = 0.f, gg2 = 0.f;
    if (ACT == 4) {
        f1 += (long)batch * CN; f2 += (long)batch * CN;
        gg1 = gam1[0]; gg2 = gam2[0];
    }

    int m0 = blockIdx.y * 64, n0 = blockIdx.x * 128;
    int tid = threadIdx.x;
    int lane = tid & 31, w = tid >> 5;
    int wm = w >> 1, wn = w & 1;           // 2x2 warp grid, 32x64 tiles
    int g = lane >> 2, t = lane & 3;

    float acc[2][8][4] = {};
    int lrow = tid >> 2, lv = tid & 3;
    int T = K >> 5;

    // ldmatrix lane address bases (bytes from sbase)
    uint32_t aAddr = sbase +
        (((wm*32 + (lane & 7) + ((lane >> 3) & 1)*8)*ROWW + ((lane >> 4) & 1)*4) << 2);
    uint32_t bAddr = sbase + (ASTG << 2) +
        (((wn*64 + (lane & 7) + ((lane >> 4) & 1)*8)*ROWW + ((lane >> 3) & 1)*4) << 2);

    auto issue = [&](int it) {
        int s = it % NSTG;
        int k0 = it * 32;
        uint32_t ab = sbase + (s*STGW)*4;
        uint32_t bb = ab + ASTG*4;
        if (!CONV3) {
            #pragma unroll
            for (int i = 0; i < 2; i++) {
                int m = i*32 + lrow;
                cp16(ab + ((m*ROWW + lv*4)*4),
                     A + (long)(m0+m)*lda + k0 + lv*8, 16);
            }
        } else {
            int tap = k0 >> 8, ci0 = k0 & 255;
            int dy = tap/3 - 1, dx = tap%3 - 1;
            #pragma unroll
            for (int i = 0; i < 2; i++) {
                int m = i*32 + lrow;
                int pix = m0 + m;
                int y = (pix >> 6) + dy, x = (pix & 63) + dx;
                bool ok = ((unsigned)y < 64u) && ((unsigned)x < 64u);
                const __half* src = ok ? (A + (long)((y<<6)+x)*lda + ci0 + lv*8) : A;
                cp16(ab + ((m*ROWW + lv*4)*4), src, ok ? 16 : 0);
            }
        }
        #pragma unroll
        for (int i = 0; i < 4; i++) {
            int n = i*32 + lrow;
            bool ok = (n0 + n) < Bn;
            const __half* src = ok ? (B + (long)(n0+n)*ldb + k0 + lv*8) : B;
            cp16(bb + ((n*ROWW + lv*4)*4), src, ok ? 16 : 0);
        }
        CP_COMMIT();
    };

    auto compute = [&](int s) {
        uint32_t soff = (uint32_t)(s*STGW) << 2;
        #pragma unroll
        for (int ks = 0; ks < 2; ks++) {
            uint32_t af[2][4], bf[8][2];
            #pragma unroll
            for (int mt = 0; mt < 2; mt++)
                ldsm4(af[mt][0], af[mt][1], af[mt][2], af[mt][3],
                      aAddr + soff + ((mt*16*ROWW + ks*8) << 2));
            #pragma unroll
            for (int p = 0; p < 4; p++) {
                uint32_t r0, r1, r2, r3;
                ldsm4(r0, r1, r2, r3,
                      bAddr + soff + ((p*16*ROWW + ks*8) << 2));
                bf[2*p][0]   = r0; bf[2*p][1]   = r1;
                bf[2*p+1][0] = r2; bf[2*p+1][1] = r3;
            }
            #pragma unroll
            for (int mt = 0; mt < 2; mt++)
                #pragma unroll
                for (int nt = 0; nt < 8; nt++)
                    mma_f16(acc[mt][nt], af[mt], bf[nt]);
        }
    };

    // prologue: 2 committed groups
    issue(0);
    if (T > 1) issue(1); else CP_COMMIT();

    for (int it = 0; it < T; it++) {
        CP_WAIT1();            // stage `it` landed
        __syncthreads();       // all warps done with slot being overwritten
        if (it + 2 < T) issue(it + 2); else CP_COMMIT();
        compute(it % NSTG);
    }

    // epilogue
    int valid = ncols - n0; if (valid > 128) valid = 128;
    #pragma unroll
    for (int mt = 0; mt < 2; mt++) {
        #pragma unroll
        for (int half_ = 0; half_ < 2; half_++) {
            int m = m0 + wm*32 + mt*16 + g + half_*8;
            float bm = (bias && bias_on_m) ? bias[m] : 0.f;
            long base = (long)m*ldc + n0;
            #pragma unroll
            for (int nt = 0; nt < 8; nt++) {
                int nl = wn*64 + nt*8 + 2*t;
                if (nl >= valid) continue;
                float v0 = acc[mt][nt][half_*2 + 0] + bm;
                float v1 = acc[mt][nt][half_*2 + 1] + bm;
                if (bias && !bias_on_m) { v0 += bias[n0+nl]; v1 += bias[n0+nl+1]; }
                if (ACT == 1) {
                    v0 = v0 / (1.f + __expf(-v0));
                    v1 = v1 / (1.f + __expf(-v1));
                    if (Caux) *(float2*)(Caux + (long)bz*sC_ + base + nl)
                              = make_float2(v0, v1);
                } else if (ACT == 4) {
                    float2 r1 = *(const float2*)(f1 + base + nl);
                    float2 r2 = *(const float2*)(f2 + base + nl);
                    v0 = 3.f*r1.x + gg1*r2.x + gg2*v0;
                    v1 = 3.f*r1.y + gg1*r2.y + gg2*v1;
                }
                st2<OutT>(C + base + nl, v0, v1);
            }
        }
    }
}

// ===================== small FMA GEMM (CoordAtt yca only) =============
__global__ __launch_bounds__(256) void gemm_small_hsw(
    const float* __restrict__ A, const float* __restrict__ B,
    const float* __restrict__ bias, float* __restrict__ C,
    int M, int N, int K, int ldb, long sB, long sC)
{
    int b = blockIdx.z;
    B += (long)b*sB; C += (long)b*sC;
    int m0 = blockIdx.y*64, n0 = blockIdx.x*64;
    __shared__ float As[16][64], Bs[16][65];
    int tid = threadIdx.x, tx = tid & 15, ty = tid >> 4;
    float acc[4][4] = {};
    for (int k0 = 0; k0 < K; k0 += 16) {
        int i = tid >> 2, jb = (tid & 3)*4, mI = m0 + i;
        #pragma unroll
        for (int j = 0; j < 4; j++) {
            int k = k0 + jb + j;
            As[jb+j][i] = (mI < M && k < K) ? A[(long)mI*K + k] : 0.f;
        }
        int jr = tid >> 4, nb = (tid & 15)*4, k = k0 + jr;
        #pragma unroll
        for (int n = 0; n < 4; n++) {
            int nn = n0 + nb + n;
            Bs[jr][nb+n] = (k < K && nn < N) ? B[(long)k*ldb + nn] : 0.f;
        }
        __syncthreads();
        #pragma unroll
        for (int j = 0; j < 16; j++) {
            float a[4], bb[4];
            #pragma unroll
            for (int i2 = 0; i2 < 4; i2++) a[i2]  = As[j][ty*4+i2];
            #pragma unroll
            for (int i2 = 0; i2 < 4; i2++) bb[i2] = Bs[j][tx*4+i2];
            #pragma unroll
            for (int i2 = 0; i2 < 4; i2++)
                #pragma unroll
                for (int jj = 0; jj < 4; jj++) acc[i2][jj] += a[i2]*bb[jj];
        }
        __syncthreads();
    }
    #pragma unroll
    for (int i = 0; i < 4; i++) {
        int mI = m0 + ty*4 + i;
        if (mI >= M) continue;
        float bv = bias ? bias[mI] : 0.f;
        #pragma unroll
        for (int jj = 0; jj < 4; jj++) {
            int n = n0 + tx*4 + jj;
            if (n >= N) continue;
            float v = acc[i][jj] + bv;
            float tq = fminf(fmaxf(v+3.f,0.f),6.f); v = v*tq*(1.f/6.f);  // h-swish
            C[(long)mI*N + n] = v;
        }
    }
}

// ===================== CoordAtt glue ==================================
__global__ void ca_pool_k(const float* __restrict__ x, float* __restrict__ pool)
{
    int c = blockIdx.x, b = blockIdx.y, t = threadIdx.x;
    const float* p = x + ((long)b*CH + c)*NPIX;
    float sh = 0.f, sw = 0.f;
    for (int i = 0; i < 64; i++) sh += p[t*64 + i];
    for (int i = 0; i < 64; i++) sw += p[i*64 + t];
    float* o = pool + ((long)b*CH + c)*128;
    o[t] = sh*(1.f/64.f); o[64+t] = sw*(1.f/64.f);
}

__global__ void ca_proj_k(const float* __restrict__ wh, const float* __restrict__ bh,
                          const float* __restrict__ ww, const float* __restrict__ bw)
{
    int hw = blockIdx.y, b = blockIdx.z;
    int idx = blockIdx.x*256 + threadIdx.x;
    int c = idx >> 6, pos = idx & 63;
    const float* W  = hw ? ww : wh;
    const float* Bi = hw ? bw : bh;
    const float* y  = g_yca + (long)b*MIPC*128 + (hw ? 64 : 0) + pos;
    float s = Bi[c];
    #pragma unroll
    for (int i = 0; i < MIPC; i++) s += W[c*MIPC + i] * y[i*128];
    float o = 1.f / (1.f + __expf(-s));
    float* dst = hw ? g_aw : g_ah;
    dst[((long)b*CH + c)*64 + pos] = o;
}

__global__ void ca_apply_k(const float* __restrict__ x)
{
    long i = blockIdx.x*256L + threadIdx.x;
    if (i >= (long)BATCH*CN) return;
    int c = (int)(i & 255); long t = i >> 8;
    int pix = (int)(t & 4095); int b = (int)(t >> 12);
    long bc = (long)b*CH + c;
    int y = pix >> 6, xx = pix & 63;
    g_r[i] = __float2half(
        x[(long)b*CN + (long)c*NPIX + pix] * g_aw[bc*64+xx] * g_ah[bc*64+y]);
}

// ============ fused maxpool 5/9/13 (one plane per block) ===============
__global__ __launch_bounds__(256) void mp_all_k(__half* __restrict__ cat)
{
    __shared__ __half2 p0[4096], p1[4096];
    int c2 = blockIdx.x, b = blockIdx.y;
    __half2* base = (__half2*)(cat + (long)b*NPIX*1024);
    int tid = threadIdx.x;
    #pragma unroll
    for (int i = tid; i < 4096; i += 256) p0[i] = base[(long)i*512 + c2];
    __syncthreads();
    #pragma unroll
    for (int pass = 1; pass <= 3; pass++) {
        #pragma unroll 4
        for (int i = tid; i < 4096; i += 256) {
            int x = i & 63;
            __half2 m = p0[i];
            if (x >= 1)  m = __hmax2(m, p0[i-1]);
            if (x >= 2)  m = __hmax2(m, p0[i-2]);
            if (x <= 62) m = __hmax2(m, p0[i+1]);
            if (x <= 61) m = __hmax2(m, p0[i+2]);
            p1[i] = m;
        }
        __syncthreads();
        #pragma unroll 4
        for (int i = tid; i < 4096; i += 256) {
            int y = i >> 6;
            __half2 m = p1[i];
            if (y >= 1)  m = __hmax2(m, p1[i-64]);
            if (y >= 2)  m = __hmax2(m, p1[i-128]);
            if (y <= 62) m = __hmax2(m, p1[i+64]);
            if (y <= 61) m = __hmax2(m, p1[i+128]);
            p0[i] = m;
            base[(long)i*512 + pass*128 + c2] = m;
        }
        __syncthreads();
    }
}

// ===================== PAM softmax (half rows of 4096) =================
__global__ void softmax_row_k(__half* __restrict__ a)
{
    __half2* p = (__half2*)(a + (long)blockIdx.x * 4096);
    int t = threadIdx.x;
    __shared__ float red[256];
    float2 v[8];
    #pragma unroll
    for (int i = 0; i < 8; i++) v[i] = __half22float2(p[t + i*256]);
    float mx = v[0].x;
    #pragma unroll
    for (int i = 0; i < 8; i++) { mx = fmaxf(mx, v[i].x); mx = fmaxf(mx, v[i].y); }
    red[t] = mx; __syncthreads();
    for (int s = 128; s > 0; s >>= 1) { if (t < s) red[t] = fmaxf(red[t], red[t+s]); __syncthreads(); }
    mx = red[0]; __syncthreads();
    float sum = 0.f;
    #pragma unroll
    for (int i = 0; i < 8; i++) {
        v[i].x = __expf(v[i].x - mx); v[i].y = __expf(v[i].y - mx);
        sum += v[i].x + v[i].y;
    }
    red[t] = sum; __syncthreads();
    for (int s = 128; s > 0; s >>= 1) { if (t < s) red[t] += red[t+s]; __syncthreads(); }
    float inv = 1.f / red[0];
    #pragma unroll
    for (int i = 0; i < 8; i++)
        p[t + i*256] = __floats2half2_rn(v[i].x * inv, v[i].y * inv);
}

// ====== CAM softmax fused with split-K reduce ==========================
__global__ void cam_softmax_k(const float* __restrict__ ep, __half* __restrict__ ac)
{
    long row = blockIdx.x;           // b*256 + c
    int b = (int)(row >> 8); int r = (int)(row & 255);
    int t = threadIdx.x;
    float v = 0.f;
    #pragma unroll
    for (int k = 0; k < ESPLIT; k++)
        v += ep[((long)(b*ESPLIT + k) << 16) + r*256 + t];
    __shared__ float sm[256];
    sm[t] = v; __syncthreads();
    for (int s = 128; s > 0; s >>= 1) { if (t < s) sm[t] = fmaxf(sm[t], sm[t+s]); __syncthreads(); }
    float rowmax = sm[0]; __syncthreads();
    float z = rowmax - v;
    sm[t] = z; __syncthreads();
    for (int s = 128; s > 0; s >>= 1) { if (t < s) sm[t] = fmaxf(sm[t], sm[t+s]); __syncthreads(); }
    float zm = sm[0]; __syncthreads();
    float pe = __expf(z - zm);
    sm[t] = pe; __syncthreads();
    for (int s = 128; s > 0; s >>= 1) { if (t < s) sm[t] += sm[t+s]; __syncthreads(); }
    ac[row*256 + t] = __float2half(pe / sm[0]);
}

// ============ tiled transpose NHWC(f32) -> NCHW f32 + half =============
__global__ void transpose_k(const float* __restrict__ src)
{
    __shared__ float s[32][33];
    int b = blockIdx.z;
    int p0 = blockIdx.x*32, c0 = blockIdx.y*32;
    int tx = threadIdx.x, ty = threadIdx.y;  // 32 x 8
    const float* S = src + (long)b*CN;
    float*  D32 = g_resT32 + (long)b*CN;
    __half* D16 = g_resT16 + (long)b*CN;
    #pragma unroll
    for (int j = 0; j < 32; j += 8)
        s[ty+j][tx] = S[(long)(p0+ty+j)*256 + c0+tx];
    __syncthreads();
    #pragma unroll
    for (int j = 0; j < 32; j += 8) {
        float v = s[tx][ty+j];
        long o = (long)(c0+ty+j)*4096 + p0+tx;
        D32[o] = v;
        D16[o] = __float2half(v);
    }
}

// ======================================================================
extern "C" void kernel_launch(void* const* d_in, const int* in_sizes, int n_in,
                              void* d_out, int out_size)
{
    const float* x     = (const float*)d_in[0];
    const float* ca_w1 = (const float*)d_in[1];
    const float* ca_b1 = (const float*)d_in[2];
    const float* ca_bn = (const float*)d_in[3];
    const float* ca_wh = (const float*)d_in[4];
    const float* ca_bh = (const float*)d_in[5];
    const float* ca_ww = (const float*)d_in[6];
    const float* ca_bw = (const float*)d_in[7];
    const float* s1_w  = (const float*)d_in[8];  const float* s1_bn = (const float*)d_in[9];
    const float* s2_w  = (const float*)d_in[10]; const float* s2_bn = (const float*)d_in[11];
    const float* s3_w  = (const float*)d_in[12]; const float* s3_bn = (const float*)d_in[13];
    const float* s4_w  = (const float*)d_in[14]; const float* s4_bn = (const float*)d_in[15];
    const float* s5_w  = (const float*)d_in[16]; const float* s5_bn = (const float*)d_in[17];
    const float* s6_w  = (const float*)d_in[18]; const float* s6_bn = (const float*)d_in[19];
    const float* s7_w  = (const float*)d_in[20]; const float* s7_bn = (const float*)d_in[21];
    const float* pq_w  = (const float*)d_in[22]; const float* pq_b  = (const float*)d_in[23];
    const float* pk_w  = (const float*)d_in[24]; const float* pk_b  = (const float*)d_in[25];
    const float* pv_w  = (const float*)d_in[26]; const float* pv_b  = (const float*)d_in[27];
    const float* gpa   = (const float*)d_in[28];
    const float* gca   = (const float*)d_in[29];

    float *pool,*yca,*res32,*pam,*epart,*w1f,*b1f,*bs1,*bs2,*bs3,*bs4,*bs5,*bs6,*bs7,*bqk;
    __half *r16,*t1,*t2,*cat,*yc,*res16,*resT16,*qk,*vb,*attn,*ac;
    __half *ws1,*ws2,*ws3,*ws4,*ws5,*ws6,*ws7,*wqk,*wpv;
    float *resT32;
    cudaGetSymbolAddress((void**)&pool, g_pool);    cudaGetSymbolAddress((void**)&yca, g_yca);
    cudaGetSymbolAddress((void**)&r16, g_r);        cudaGetSymbolAddress((void**)&t1, g_t1);
    cudaGetSymbolAddress((void**)&t2, g_t2);        cudaGetSymbolAddress((void**)&cat, g_cat);
    cudaGetSymbolAddress((void**)&yc, g_yc);
    cudaGetSymbolAddress((void**)&res16, g_res16);  cudaGetSymbolAddress((void**)&res32, g_res32);
    cudaGetSymbolAddress((void**)&resT16, g_resT16);cudaGetSymbolAddress((void**)&resT32, g_resT32);
    cudaGetSymbolAddress((void**)&qk, g_qk);        cudaGetSymbolAddress((void**)&vb, g_v);
    cudaGetSymbolAddress((void**)&attn, g_attn);    cudaGetSymbolAddress((void**)&pam, g_pam);
    cudaGetSymbolAddress((void**)&epart, g_epart);  cudaGetSymbolAddress((void**)&ac, g_ac);
    cudaGetSymbolAddress((void**)&w1f, g_w1f);      cudaGetSymbolAddress((void**)&b1f, g_b1f);
    cudaGetSymbolAddress((void**)&ws1, g_ws1);      cudaGetSymbolAddress((void**)&bs1, g_bs1);
    cudaGetSymbolAddress((void**)&ws2, g_ws2);      cudaGetSymbolAddress((void**)&bs2, g_bs2);
    cudaGetSymbolAddress((void**)&ws3, g_ws3);      cudaGetSymbolAddress((void**)&bs3, g_bs3);
    cudaGetSymbolAddress((void**)&ws4, g_ws4);      cudaGetSymbolAddress((void**)&bs4, g_bs4);
    cudaGetSymbolAddress((void**)&ws5, g_ws5);      cudaGetSymbolAddress((void**)&bs5, g_bs5);
    cudaGetSymbolAddress((void**)&ws6, g_ws6);      cudaGetSymbolAddress((void**)&bs6, g_bs6);
    cudaGetSymbolAddress((void**)&ws7, g_ws7);      cudaGetSymbolAddress((void**)&bs7, g_bs7);
    cudaGetSymbolAddress((void**)&wqk, g_wqk);      cudaGetSymbolAddress((void**)&bqk, g_bqk);
    cudaGetSymbolAddress((void**)&wpv, g_wpv);

    const int SMEMSZ = SMEM_WORDS * 4;   // 46080 B
    cudaFuncSetAttribute(mma_gemm<0,false,__half>, cudaFuncAttributeMaxDynamicSharedMemorySize, SMEMSZ);
    cudaFuncSetAttribute(mma_gemm<0,false,float>,  cudaFuncAttributeMaxDynamicSharedMemorySize, SMEMSZ);
    cudaFuncSetAttribute(mma_gemm<1,false,__half>, cudaFuncAttributeMaxDynamicSharedMemorySize, SMEMSZ);
    cudaFuncSetAttribute(mma_gemm<1,true,__half>,  cudaFuncAttributeMaxDynamicSharedMemorySize, SMEMSZ);
    cudaFuncSetAttribute(mma_gemm<4,false,float>,  cudaFuncAttributeMaxDynamicSharedMemorySize, SMEMSZ);

    const int EB  = (BATCH*CN + 255)/256;

    // ---- merged fold/convert ----
    FoldArgs fa;
    fa.w[0]=ca_w1; fa.bn[0]=ca_bn; fa.bin[0]=ca_b1; fa.wf[0]=nullptr; fa.bf[0]=b1f; fa.O[0]=MIPC; fa.Ke[0]=256;  fa.ro[0]=0;
    fa.w[1]=s1_w;  fa.bn[1]=s1_bn; fa.bin[1]=nullptr; fa.wf[1]=ws1; fa.bf[1]=bs1; fa.O[1]=CH; fa.Ke[1]=256;  fa.ro[1]=0;
    fa.w[2]=s2_w;  fa.bn[2]=s2_bn; fa.bin[2]=nullptr; fa.wf[2]=ws2; fa.bf[2]=bs2; fa.O[2]=CH; fa.Ke[2]=256;  fa.ro[2]=0;
    fa.w[3]=s3_w;  fa.bn[3]=s3_bn; fa.bin[3]=nullptr; fa.wf[3]=ws3; fa.bf[3]=bs3; fa.O[3]=CH; fa.Ke[3]=2304; fa.ro[3]=1;
    fa.w[4]=s4_w;  fa.bn[4]=s4_bn; fa.bin[4]=nullptr; fa.wf[4]=ws4; fa.bf[4]=bs4; fa.O[4]=CH; fa.Ke[4]=256;  fa.ro[4]=0;
    fa.w[5]=s5_w;  fa.bn[5]=s5_bn; fa.bin[5]=nullptr; fa.wf[5]=ws5; fa.bf[5]=bs5; fa.O[5]=CH; fa.Ke[5]=1024; fa.ro[5]=0;
    fa.w[6]=s6_w;  fa.bn[6]=s6_bn; fa.bin[6]=nullptr; fa.wf[6]=ws6; fa.bf[6]=bs6; fa.O[6]=CH; fa.Ke[6]=2304; fa.ro[6]=1;
    fa.w[7]=s7_w;  fa.bn[7]=s7_bn; fa.bin[7]=nullptr; fa.wf[7]=ws7; fa.bf[7]=bs7; fa.O[7]=CH; fa.Ke[7]=512;  fa.ro[7]=0;
    fa.w1f_f=w1f;
    fa.pq_w=pq_w; fa.pq_b=pq_b; fa.pk_w=pk_w; fa.pk_b=pk_b; fa.pv_w=pv_w;
    fa.qkw=wqk; fa.qkb=bqk; fa.pvw=wpv;
    fold_all_k<<<dim3(256,10),256>>>(fa);

    // ---- CoordAtt ----
    ca_pool_k<<<dim3(CH,BATCH),64>>>(x, pool);
    gemm_small_hsw<<<dim3(2,1,BATCH),256>>>(w1f, pool, b1f, yca,
        MIPC,128,CH, 128, (long)CH*128, (long)MIPC*128);
    ca_proj_k<<<dim3(64,2,BATCH),256>>>(ca_wh, ca_bh, ca_ww, ca_bw);
    ca_apply_k<<<EB,256>>>(x);

    // ---- SPPCSPC ----
    mma_gemm<1,false,__half><<<dim3(2,64,BATCH),128,SMEMSZ>>>(r16, ws1, bs1, t1,
        256,256,256,256, 256,256,0, (long)CN,0,(long)CN);
    mma_gemm<1,true,__half><<<dim3(2,64,BATCH),128,SMEMSZ>>>(t1, ws3, bs3, t2,
        2304,256,2304,256, 256,256,0, (long)CN,0,(long)CN);
    mma_gemm<1,false,__half><<<dim3(2,64,BATCH),128,SMEMSZ>>>(t2, ws4, bs4, cat,
        256,256,256,1024, 256,256,0, (long)CN,0,(long)NPIX*1024);
    mp_all_k<<<dim3(128,BATCH),256>>>(cat);
    mma_gemm<1,false,__half><<<dim3(2,64,BATCH),128,SMEMSZ>>>(cat, ws5, bs5, t1,
        1024,1024,1024,256, 256,256,0, (long)NPIX*1024,0,(long)CN);
    mma_gemm<1,true,__half><<<dim3(2,64,BATCH),128,SMEMSZ>>>(t1, ws6, bs6, yc,
        2304,256,2304,512, 256,256,0, (long)CN,0,(long)NPIX*512);
    mma_gemm<1,false,__half><<<dim3(2,64,BATCH),128,SMEMSZ>>>(r16, ws2, bs2, yc+256,
        256,256,256,512, 256,256,0, (long)CN,0,(long)NPIX*512);
    mma_gemm<1,false,__half><<<dim3(2,64,BATCH),128,SMEMSZ>>>(yc, ws7, bs7, res16,
        512,512,512,256, 256,256,0, (long)NPIX*512,0,(long)CN, 1, res32);

    // ---- PAM ----
    mma_gemm<0,false,__half><<<dim3(1,64,BATCH),128,SMEMSZ>>>(res16, wqk, bqk, qk,
        256,256,256,64, 64,64,0, (long)CN,0,(long)NPIX*64);
    mma_gemm<0,false,__half><<<dim3(32,4,BATCH),128,SMEMSZ>>>(wpv, res16, pv_b, vb,
        256,256,256,NPIX, NPIX,NPIX,1, 0,(long)CN,(long)CN);
    mma_gemm<0,false,__half><<<dim3(32,64,BATCH),128,SMEMSZ>>>(qk, qk+32, nullptr, attn,
        CQD,64,64,NPIX, NPIX,NPIX,0, (long)NPIX*64,(long)NPIX*64,(long)NPIX*NPIX);
    softmax_row_k<<<BATCH*NPIX,256>>>(attn);
    mma_gemm<0,false,float><<<dim3(32,4,BATCH),128,SMEMSZ>>>(vb, attn, nullptr, pam,
        NPIX,NPIX,NPIX,NPIX, NPIX,NPIX,0, (long)CN,(long)NPIX*NPIX,(long)CN);

    // ---- CAM ----
    transpose_k<<<dim3(128,8,BATCH),dim3(32,8)>>>(res32);
    mma_gemm<0,false,float><<<dim3(2,4,BATCH*ESPLIT),128,SMEMSZ>>>(resT16, resT16, nullptr, epart,
        NPIX/ESPLIT,NPIX,NPIX,256, 256,256,0, (long)CN,(long)CN,(long)CH*CH, ESPLIT);
    cam_softmax_k<<<BATCH*CH,256>>>(epart, ac);
    mma_gemm<4,false,float><<<dim3(32,4,BATCH),128,SMEMSZ>>>(ac, res16, nullptr, (float*)d_out,
        256,256,256,NPIX, NPIX,NPIX,0, (long)CH*CH,(long)CN,(long)CN,
        1, nullptr, resT32, pam, gpa, gca);
}

// round 15
// speedup vs baseline: 1.0915x; 1.0299x over previous
#include <cuda_runtime.h>
#include <cuda_fp16.h>
#include <cstdint>

// Problem constants
#define BATCH 2
#define CH    256
#define NPIX  4096
#define MIPC  8
#define CQD   32
#define CN    (CH*NPIX)
#define ESPLIT 8

// ===================== static scratch ==================================
__device__ float  g_pool[BATCH*CH*128];
__device__ float  g_yca [BATCH*MIPC*128];
__device__ float  g_ah  [BATCH*CH*64];
__device__ float  g_aw  [BATCH*CH*64];
__device__ __half g_r   [BATCH*CN];              // NHWC half
__device__ __half g_t1  [BATCH*CN];
__device__ __half g_t2  [BATCH*CN];
__device__ __half g_cat [(long)BATCH*NPIX*1024];
__device__ __half g_yc  [(long)BATCH*NPIX*512];
__device__ __half g_res16[BATCH*CN];             // NHWC half (operand)
__device__ float  g_res32[BATCH*CN];             // NHWC f32 (residual)
__device__ __half g_resT16[BATCH*CN];            // NCHW half (e GEMM)
__device__ float  g_resT32[BATCH*CN];            // NCHW f32 (final residual)
__device__ __half g_qk  [BATCH*NPIX*64];
__device__ __half g_v   [BATCH*CN];              // NCHW half
__device__ __half g_attn[(long)BATCH*NPIX*NPIX]; // 64 MB half
__device__ float  g_pam [BATCH*CN];              // NCHW f32
__device__ float  g_epart[BATCH*ESPLIT*CH*CH];
__device__ __half g_ac  [BATCH*CH*CH];
// folded weights (half) + biases (f32)
__device__ float  g_w1f[MIPC*CH];   __device__ float g_b1f[MIPC];
__device__ __half g_ws1[CH*CH];     __device__ float g_bs1[CH];
__device__ __half g_ws2[CH*CH];     __device__ float g_bs2[CH];
__device__ __half g_ws3[CH*2304];   __device__ float g_bs3[CH];
__device__ __half g_ws4[CH*CH];     __device__ float g_bs4[CH];
__device__ __half g_ws5[CH*1024];   __device__ float g_bs5[CH];
__device__ __half g_ws6[CH*2304];   __device__ float g_bs6[CH];
__device__ __half g_ws7[CH*512];    __device__ float g_bs7[CH];
__device__ __half g_wqk[64*CH];     __device__ float g_bqk[64];
__device__ __half g_wpv[CH*CH];

// ===================== merged fold/convert (1 launch) ==================
struct FoldArgs {
    const float* w[8]; const float* bn[8]; const float* bin[8];
    __half* wf[8]; float* bf[8];
    int O[8]; int Ke[8]; int ro[8];
    float* w1f_f;
    const float *pq_w, *pq_b, *pk_w, *pk_b, *pv_w;
    __half *qkw, *pvw;
    float *qkb;
};

__global__ void fold_all_k(FoldArgs a)
{
    int j = blockIdx.y, o = blockIdx.x;
    if (j == 8) {
        if (o >= 64) return;
        const float* src = (o < 32) ? (a.pq_w + (long)o*256)
                                    : (a.pk_w + (long)(o-32)*256);
        for (int k = threadIdx.x; k < 256; k += blockDim.x)
            a.qkw[(long)o*256 + k] = __float2half(src[k]);
        if (threadIdx.x == 0)
            a.qkb[o] = (o < 32) ? a.pq_b[o] : a.pk_b[o-32];
        return;
    }
    if (j == 9) {
        for (int k = threadIdx.x; k < 256; k += blockDim.x)
            a.pvw[(long)o*256 + k] = __float2half(a.pv_w[(long)o*256 + k]);
        return;
    }
    int O = a.O[j];
    if (o >= O) return;
    const float* bn = a.bn[j];
    float g  = bn[o], be = bn[O+o], mn = bn[2*O+o], vr = bn[3*O+o];
    float s = g * rsqrtf(vr + 1e-5f);
    int Ke = a.Ke[j];
    const float* w = a.w[j];
    if (j == 0) {
        for (int k = threadIdx.x; k < Ke; k += blockDim.x)
            a.w1f_f[(long)o*Ke + k] = w[(long)o*Ke + k] * s;
    } else if (a.ro[j]) {
        __half* wf = a.wf[j];
        for (int k = threadIdx.x; k < Ke; k += blockDim.x) {
            int t = k >> 8, ci = k & 255;
            wf[(long)o*Ke + k] = __float2half(w[((long)o*256 + ci)*9 + t] * s);
        }
    } else {
        __half* wf = a.wf[j];
        for (int k = threadIdx.x; k < Ke; k += blockDim.x)
            wf[(long)o*Ke + k] = __float2half(w[(long)o*Ke + k] * s);
    }
    if (threadIdx.x == 0)
        a.bf[j][o] = (a.bin[j] ? a.bin[j][o] : 0.f) * s + be - mn * s;
}

// ===================== fp16 mma.sync primitives ========================
__device__ __forceinline__ void mma_f16(float c[4], const uint32_t a[4],
                                        const uint32_t b[2]) {
    asm volatile(
        "mma.sync.aligned.m16n8k16.row.col.f32.f16.f16.f32 "
        "{%0,%1,%2,%3}, {%4,%5,%6,%7}, {%8,%9}, {%0,%1,%2,%3};"
        : "+f"(c[0]), "+f"(c[1]), "+f"(c[2]), "+f"(c[3])
        : "r"(a[0]), "r"(a[1]), "r"(a[2]), "r"(a[3]), "r"(b[0]), "r"(b[1]));
}
__device__ __forceinline__ void ldsm4(uint32_t& r0, uint32_t& r1,
                                      uint32_t& r2, uint32_t& r3, uint32_t addr) {
    asm volatile("ldmatrix.sync.aligned.m8n8.x4.shared.b16 {%0,%1,%2,%3}, [%4];"
                 : "=r"(r0), "=r"(r1), "=r"(r2), "=r"(r3) : "r"(addr));
}
__device__ __forceinline__ void cp16(uint32_t dst, const void* src, int srcsize) {
    asm volatile("cp.async.cg.shared.global [%0], [%1], 16, %2;"
                 :: "r"(dst), "l"(src), "r"(srcsize));
}
#define CP_COMMIT() asm volatile("cp.async.commit_group;" ::: "memory")
#define CP_WAIT1()  asm volatile("cp.async.wait_group 1;" ::: "memory")

// SMEM rows: 32 halves data + 8 halves pad = 20 words
// Block tile 64(M) x 128(N): A stage 64 rows, B stage 128 rows
#define ROWW 20
#define ASTG (64*ROWW)           // 1280 words
#define BSTG (128*ROWW)          // 2560 words
#define STGW (ASTG+BSTG)         // 3840 words per stage
#define NSTG 3
#define SMEM_WORDS (NSTG*STGW)   // 11520 words = 46 KB

template<typename OutT>
__device__ __forceinline__ void st2(OutT* p, float v0, float v1);
template<> __device__ __forceinline__ void st2<__half>(__half* p, float v0, float v1) {
    *(__half2*)p = __floats2half2_rn(v0, v1);
}
template<> __device__ __forceinline__ void st2<float>(float* p, float v0, float v1) {
    *(float2*)p = make_float2(v0, v1);
}

// D[m0..+63][n0..+127] = act( sum_k A[m][k]*B[n][k] + bias )  (half in)
// ACT: 0 none, 1 SiLU (+opt f32 aux), 4 final combine
template<int ACT, bool CONV3, typename OutT>
__global__ __launch_bounds__(128) void mma_gemm(
    const __half* __restrict__ A, const __half* __restrict__ B,
    const float* __restrict__ bias, OutT* __restrict__ C,
    int K, int lda, int ldb, int ldc, int Bn, int ncols, int bias_on_m,
    long sA_, long sB_, long sC_,
    int nsplit = 1, float* __restrict__ Caux = nullptr,
    const float* __restrict__ f1 = nullptr, const float* __restrict__ f2 = nullptr,
    const float* __restrict__ gam1 = nullptr, const float* __restrict__ gam2 = nullptr)
{
    extern __shared__ uint32_t smu[];
    uint32_t sbase = (uint32_t)__cvta_generic_to_shared(smu);

    int bz = blockIdx.z;
    int batch = bz, slice = 0;
    if (nsplit > 1) { batch = bz / nsplit; slice = bz - batch * nsplit; }
    A += batch * sA_ + (long)slice * K;
    B += batch * sB_ + (long)slice * K;
    C += (long)bz * sC_;
    float gg1 = 0.f, gg2 = 0.f;
    if (ACT == 4) {
        f1 += (long)batch * CN; f2 += (long)batch * CN;
        gg1 = gam1[0]; gg2 = gam2[0];
    }

    int m0 = blockIdx.y * 64, n0 = blockIdx.x * 128;
    int tid = threadIdx.x;
    int lane = tid & 31, w = tid >> 5;
    int wm = w >> 1, wn = w & 1;           // 2x2 warp grid, 32x64 tiles
    int g = lane >> 2, t = lane & 3;

    float acc[2][8][4] = {};
    int lrow = tid >> 2, lv = tid & 3;
    int T = K >> 5;

    // ldmatrix lane address bases (bytes from sbase)
    uint32_t aAddr = sbase +
        (((wm*32 + (lane & 7) + ((lane >> 3) & 1)*8)*ROWW + ((lane >> 4) & 1)*4) << 2);
    uint32_t bAddr = sbase + (ASTG << 2) +
        (((wn*64 + (lane & 7) + ((lane >> 4) & 1)*8)*ROWW + ((lane >> 3) & 1)*4) << 2);

    auto issue = [&](int it) {
        int s = it % NSTG;
        int k0 = it * 32;
        uint32_t ab = sbase + (s*STGW)*4;
        uint32_t bb = ab + ASTG*4;
        if (!CONV3) {
            #pragma unroll
            for (int i = 0; i < 2; i++) {
                int m = i*32 + lrow;
                cp16(ab + ((m*ROWW + lv*4)*4),
                     A + (long)(m0+m)*lda + k0 + lv*8, 16);
            }
        } else {
            int tap = k0 >> 8, ci0 = k0 & 255;
            int dy = tap/3 - 1, dx = tap%3 - 1;
            #pragma unroll
            for (int i = 0; i < 2; i++) {
                int m = i*32 + lrow;
                int pix = m0 + m;
                int y = (pix >> 6) + dy, x = (pix & 63) + dx;
                bool ok = ((unsigned)y < 64u) && ((unsigned)x < 64u);
                const __half* src = ok ? (A + (long)((y<<6)+x)*lda + ci0 + lv*8) : A;
                cp16(ab + ((m*ROWW + lv*4)*4), src, ok ? 16 : 0);
            }
        }
        #pragma unroll
        for (int i = 0; i < 4; i++) {
            int n = i*32 + lrow;
            bool ok = (n0 + n) < Bn;
            const __half* src = ok ? (B + (long)(n0+n)*ldb + k0 + lv*8) : B;
            cp16(bb + ((n*ROWW + lv*4)*4), src, ok ? 16 : 0);
        }
        CP_COMMIT();
    };

    auto compute = [&](int s) {
        uint32_t soff = (uint32_t)(s*STGW) << 2;
        #pragma unroll
        for (int ks = 0; ks < 2; ks++) {
            uint32_t af[2][4], bf[8][2];
            #pragma unroll
            for (int mt = 0; mt < 2; mt++)
                ldsm4(af[mt][0], af[mt][1], af[mt][2], af[mt][3],
                      aAddr + soff + ((mt*16*ROWW + ks*8) << 2));
            #pragma unroll
            for (int p = 0; p < 4; p++) {
                uint32_t r0, r1, r2, r3;
                ldsm4(r0, r1, r2, r3,
                      bAddr + soff + ((p*16*ROWW + ks*8) << 2));
                bf[2*p][0]   = r0; bf[2*p][1]   = r1;
                bf[2*p+1][0] = r2; bf[2*p+1][1] = r3;
            }
            #pragma unroll
            for (int mt = 0; mt < 2; mt++)
                #pragma unroll
                for (int nt = 0; nt < 8; nt++)
                    mma_f16(acc[mt][nt], af[mt], bf[nt]);
        }
    };

    // prologue: 2 committed groups
    issue(0);
    if (T > 1) issue(1); else CP_COMMIT();

    for (int it = 0; it < T; it++) {
        CP_WAIT1();            // stage `it` landed
        __syncthreads();       // all warps done with slot being overwritten
        if (it + 2 < T) issue(it + 2); else CP_COMMIT();
        compute(it % NSTG);
    }

    // epilogue
    int valid = ncols - n0; if (valid > 128) valid = 128;
    #pragma unroll
    for (int mt = 0; mt < 2; mt++) {
        #pragma unroll
        for (int half_ = 0; half_ < 2; half_++) {
            int m = m0 + wm*32 + mt*16 + g + half_*8;
            float bm = (bias && bias_on_m) ? bias[m] : 0.f;
            long base = (long)m*ldc + n0;
            #pragma unroll
            for (int nt = 0; nt < 8; nt++) {
                int nl = wn*64 + nt*8 + 2*t;
                if (nl >= valid) continue;
                float v0 = acc[mt][nt][half_*2 + 0] + bm;
                float v1 = acc[mt][nt][half_*2 + 1] + bm;
                if (bias && !bias_on_m) { v0 += bias[n0+nl]; v1 += bias[n0+nl+1]; }
                if (ACT == 1) {
                    v0 = v0 / (1.f + __expf(-v0));
                    v1 = v1 / (1.f + __expf(-v1));
                    if (Caux) *(float2*)(Caux + (long)bz*sC_ + base + nl)
                              = make_float2(v0, v1);
                } else if (ACT == 4) {
                    float2 r1 = *(const float2*)(f1 + base + nl);
                    float2 r2 = *(const float2*)(f2 + base + nl);
                    v0 = 3.f*r1.x + gg1*r2.x + gg2*v0;
                    v1 = 3.f*r1.y + gg1*r2.y + gg2*v1;
                }
                st2<OutT>(C + base + nl, v0, v1);
            }
        }
    }
}

// ===================== small FMA GEMM (CoordAtt yca only) =============
__global__ __launch_bounds__(256) void gemm_small_hsw(
    const float* __restrict__ A, const float* __restrict__ B,
    const float* __restrict__ bias, float* __restrict__ C,
    int M, int N, int K, int ldb, long sB, long sC)
{
    int b = blockIdx.z;
    B += (long)b*sB; C += (long)b*sC;
    int m0 = blockIdx.y*64, n0 = blockIdx.x*64;
    __shared__ float As[16][64], Bs[16][65];
    int tid = threadIdx.x, tx = tid & 15, ty = tid >> 4;
    float acc[4][4] = {};
    for (int k0 = 0; k0 < K; k0 += 16) {
        int i = tid >> 2, jb = (tid & 3)*4, mI = m0 + i;
        #pragma unroll
        for (int j = 0; j < 4; j++) {
            int k = k0 + jb + j;
            As[jb+j][i] = (mI < M && k < K) ? A[(long)mI*K + k] : 0.f;
        }
        int jr = tid >> 4, nb = (tid & 15)*4, k = k0 + jr;
        #pragma unroll
        for (int n = 0; n < 4; n++) {
            int nn = n0 + nb + n;
            Bs[jr][nb+n] = (k < K && nn < N) ? B[(long)k*ldb + nn] : 0.f;
        }
        __syncthreads();
        #pragma unroll
        for (int j = 0; j < 16; j++) {
            float a[4], bb[4];
            #pragma unroll
            for (int i2 = 0; i2 < 4; i2++) a[i2]  = As[j][ty*4+i2];
            #pragma unroll
            for (int i2 = 0; i2 < 4; i2++) bb[i2] = Bs[j][tx*4+i2];
            #pragma unroll
            for (int i2 = 0; i2 < 4; i2++)
                #pragma unroll
                for (int jj = 0; jj < 4; jj++) acc[i2][jj] += a[i2]*bb[jj];
        }
        __syncthreads();
    }
    #pragma unroll
    for (int i = 0; i < 4; i++) {
        int mI = m0 + ty*4 + i;
        if (mI >= M) continue;
        float bv = bias ? bias[mI] : 0.f;
        #pragma unroll
        for (int jj = 0; jj < 4; jj++) {
            int n = n0 + tx*4 + jj;
            if (n >= N) continue;
            float v = acc[i][jj] + bv;
            float tq = fminf(fmaxf(v+3.f,0.f),6.f); v = v*tq*(1.f/6.f);  // h-swish
            C[(long)mI*N + n] = v;
        }
    }
}

// ===================== CoordAtt glue (coalesced) ======================
__global__ void ca_pool_k(const float* __restrict__ x, float* __restrict__ pool)
{
    __shared__ float s[64][65];
    int c = blockIdx.x, b = blockIdx.y, t = threadIdx.x;   // t < 64
    const float* p = x + ((long)b*CH + c)*NPIX;
    for (int i = 0; i < 64; i++) s[i][t] = p[i*64 + t];    // coalesced
    __syncthreads();
    float sh = 0.f, sw = 0.f;
    for (int i = 0; i < 64; i++) { sh += s[t][i]; sw += s[i][t]; }
    float* o = pool + ((long)b*CH + c)*128;
    o[t] = sh*(1.f/64.f); o[64+t] = sw*(1.f/64.f);
}

__global__ void ca_proj_k(const float* __restrict__ wh, const float* __restrict__ bh,
                          const float* __restrict__ ww, const float* __restrict__ bw)
{
    int hw = blockIdx.y, b = blockIdx.z;
    int idx = blockIdx.x*256 + threadIdx.x;
    int c = idx >> 6, pos = idx & 63;
    const float* W  = hw ? ww : wh;
    const float* Bi = hw ? bw : bh;
    const float* y  = g_yca + (long)b*MIPC*128 + (hw ? 64 : 0) + pos;
    float s = Bi[c];
    #pragma unroll
    for (int i = 0; i < MIPC; i++) s += W[c*MIPC + i] * y[i*128];
    float o = 1.f / (1.f + __expf(-s));
    float* dst = hw ? g_aw : g_ah;
    dst[((long)b*CH + c)*64 + pos] = o;
}

// tiled NCHW->NHWC apply: coalesced reads along pix, coalesced writes along c
__global__ void ca_apply_k(const float* __restrict__ x)
{
    __shared__ float s[32][33];
    int b = blockIdx.z;
    int p0 = blockIdx.x*32, c0 = blockIdx.y*32;
    int tx = threadIdx.x, ty = threadIdx.y;   // 32 x 8
    const float* X = x + (long)b*CN;
    __half* R = g_r + (long)b*CN;
    #pragma unroll
    for (int j = 0; j < 32; j += 8)
        s[ty+j][tx] = X[(long)(c0+ty+j)*4096 + p0+tx];
    __syncthreads();
    #pragma unroll
    for (int j = 0; j < 32; j += 8) {
        int pix = p0 + ty + j;
        int c = c0 + tx;
        long bc = (long)b*CH + c;
        float v = s[tx][ty+j] * g_aw[bc*64 + (pix & 63)] * g_ah[bc*64 + (pix >> 6)];
        R[(long)pix*256 + c] = __float2half(v);
    }
}

// ============ fused maxpool 5/9/13 (one plane per block) ===============
__global__ __launch_bounds__(256) void mp_all_k(__half* __restrict__ cat)
{
    __shared__ __half2 p0[4096], p1[4096];
    int c2 = blockIdx.x, b = blockIdx.y;
    __half2* base = (__half2*)(cat + (long)b*NPIX*1024);
    int tid = threadIdx.x;
    #pragma unroll
    for (int i = tid; i < 4096; i += 256) p0[i] = base[(long)i*512 + c2];
    __syncthreads();
    #pragma unroll
    for (int pass = 1; pass <= 3; pass++) {
        #pragma unroll 4
        for (int i = tid; i < 4096; i += 256) {
            int x = i & 63;
            __half2 m = p0[i];
            if (x >= 1)  m = __hmax2(m, p0[i-1]);
            if (x >= 2)  m = __hmax2(m, p0[i-2]);
            if (x <= 62) m = __hmax2(m, p0[i+1]);
            if (x <= 61) m = __hmax2(m, p0[i+2]);
            p1[i] = m;
        }
        __syncthreads();
        #pragma unroll 4
        for (int i = tid; i < 4096; i += 256) {
            int y = i >> 6;
            __half2 m = p1[i];
            if (y >= 1)  m = __hmax2(m, p1[i-64]);
            if (y >= 2)  m = __hmax2(m, p1[i-128]);
            if (y <= 62) m = __hmax2(m, p1[i+64]);
            if (y <= 61) m = __hmax2(m, p1[i+128]);
            p0[i] = m;
            base[(long)i*512 + pass*128 + c2] = m;
        }
        __syncthreads();
    }
}

// ===================== PAM softmax (half rows of 4096) =================
__global__ void softmax_row_k(__half* __restrict__ a)
{
    __half2* p = (__half2*)(a + (long)blockIdx.x * 4096);
    int t = threadIdx.x;
    __shared__ float red[256];
    float2 v[8];
    #pragma unroll
    for (int i = 0; i < 8; i++) v[i] = __half22float2(p[t + i*256]);
    float mx = v[0].x;
    #pragma unroll
    for (int i = 0; i < 8; i++) { mx = fmaxf(mx, v[i].x); mx = fmaxf(mx, v[i].y); }
    red[t] = mx; __syncthreads();
    for (int s = 128; s > 0; s >>= 1) { if (t < s) red[t] = fmaxf(red[t], red[t+s]); __syncthreads(); }
    mx = red[0]; __syncthreads();
    float sum = 0.f;
    #pragma unroll
    for (int i = 0; i < 8; i++) {
        v[i].x = __expf(v[i].x - mx); v[i].y = __expf(v[i].y - mx);
        sum += v[i].x + v[i].y;
    }
    red[t] = sum; __syncthreads();
    for (int s = 128; s > 0; s >>= 1) { if (t < s) red[t] += red[t+s]; __syncthreads(); }
    float inv = 1.f / red[0];
    #pragma unroll
    for (int i = 0; i < 8; i++)
        p[t + i*256] = __floats2half2_rn(v[i].x * inv, v[i].y * inv);
}

// ====== CAM softmax fused with split-K reduce ==========================
__global__ void cam_softmax_k(const float* __restrict__ ep, __half* __restrict__ ac)
{
    long row = blockIdx.x;           // b*256 + c
    int b = (int)(row >> 8); int r = (int)(row & 255);
    int t = threadIdx.x;
    float v = 0.f;
    #pragma unroll
    for (int k = 0; k < ESPLIT; k++)
        v += ep[((long)(b*ESPLIT + k) << 16) + r*256 + t];
    __shared__ float sm[256];
    sm[t] = v; __syncthreads();
    for (int s = 128; s > 0; s >>= 1) { if (t < s) sm[t] = fmaxf(sm[t], sm[t+s]); __syncthreads(); }
    float rowmax = sm[0]; __syncthreads();
    float z = rowmax - v;
    sm[t] = z; __syncthreads();
    for (int s = 128; s > 0; s >>= 1) { if (t < s) sm[t] = fmaxf(sm[t], sm[t+s]); __syncthreads(); }
    float zm = sm[0]; __syncthreads();
    float pe = __expf(z - zm);
    sm[t] = pe; __syncthreads();
    for (int s = 128; s > 0; s >>= 1) { if (t < s) sm[t] += sm[t+s]; __syncthreads(); }
    ac[row*256 + t] = __float2half(pe / sm[0]);
}

// ============ tiled transpose NHWC(f32) -> NCHW f32 + half =============
__global__ void transpose_k(const float* __restrict__ src)
{
    __shared__ float s[32][33];
    int b = blockIdx.z;
    int p0 = blockIdx.x*32, c0 = blockIdx.y*32;
    int tx = threadIdx.x, ty = threadIdx.y;  // 32 x 8
    const float* S = src + (long)b*CN;
    float*  D32 = g_resT32 + (long)b*CN;
    __half* D16 = g_resT16 + (long)b*CN;
    #pragma unroll
    for (int j = 0; j < 32; j += 8)
        s[ty+j][tx] = S[(long)(p0+ty+j)*256 + c0+tx];
    __syncthreads();
    #pragma unroll
    for (int j = 0; j < 32; j += 8) {
        float v = s[tx][ty+j];
        long o = (long)(c0+ty+j)*4096 + p0+tx;
        D32[o] = v;
        D16[o] = __float2half(v);
    }
}

// ======================================================================
extern "C" void kernel_launch(void* const* d_in, const int* in_sizes, int n_in,
                              void* d_out, int out_size)
{
    const float* x     = (const float*)d_in[0];
    const float* ca_w1 = (const float*)d_in[1];
    const float* ca_b1 = (const float*)d_in[2];
    const float* ca_bn = (const float*)d_in[3];
    const float* ca_wh = (const float*)d_in[4];
    const float* ca_bh = (const float*)d_in[5];
    const float* ca_ww = (const float*)d_in[6];
    const float* ca_bw = (const float*)d_in[7];
    const float* s1_w  = (const float*)d_in[8];  const float* s1_bn = (const float*)d_in[9];
    const float* s2_w  = (const float*)d_in[10]; const float* s2_bn = (const float*)d_in[11];
    const float* s3_w  = (const float*)d_in[12]; const float* s3_bn = (const float*)d_in[13];
    const float* s4_w  = (const float*)d_in[14]; const float* s4_bn = (const float*)d_in[15];
    const float* s5_w  = (const float*)d_in[16]; const float* s5_bn = (const float*)d_in[17];
    const float* s6_w  = (const float*)d_in[18]; const float* s6_bn = (const float*)d_in[19];
    const float* s7_w  = (const float*)d_in[20]; const float* s7_bn = (const float*)d_in[21];
    const float* pq_w  = (const float*)d_in[22]; const float* pq_b  = (const float*)d_in[23];
    const float* pk_w  = (const float*)d_in[24]; const float* pk_b  = (const float*)d_in[25];
    const float* pv_w  = (const float*)d_in[26]; const float* pv_b  = (const float*)d_in[27];
    const float* gpa   = (const float*)d_in[28];
    const float* gca   = (const float*)d_in[29];

    float *pool,*yca,*res32,*pam,*epart,*w1f,*b1f,*bs1,*bs2,*bs3,*bs4,*bs5,*bs6,*bs7,*bqk;
    __half *r16,*t1,*t2,*cat,*yc,*res16,*resT16,*qk,*vb,*attn,*ac;
    __half *ws1,*ws2,*ws3,*ws4,*ws5,*ws6,*ws7,*wqk,*wpv;
    float *resT32;
    cudaGetSymbolAddress((void**)&pool, g_pool);    cudaGetSymbolAddress((void**)&yca, g_yca);
    cudaGetSymbolAddress((void**)&r16, g_r);        cudaGetSymbolAddress((void**)&t1, g_t1);
    cudaGetSymbolAddress((void**)&t2, g_t2);        cudaGetSymbolAddress((void**)&cat, g_cat);
    cudaGetSymbolAddress((void**)&yc, g_yc);
    cudaGetSymbolAddress((void**)&res16, g_res16);  cudaGetSymbolAddress((void**)&res32, g_res32);
    cudaGetSymbolAddress((void**)&resT16, g_resT16);cudaGetSymbolAddress((void**)&resT32, g_resT32);
    cudaGetSymbolAddress((void**)&qk, g_qk);        cudaGetSymbolAddress((void**)&vb, g_v);
    cudaGetSymbolAddress((void**)&attn, g_attn);    cudaGetSymbolAddress((void**)&pam, g_pam);
    cudaGetSymbolAddress((void**)&epart, g_epart);  cudaGetSymbolAddress((void**)&ac, g_ac);
    cudaGetSymbolAddress((void**)&w1f, g_w1f);      cudaGetSymbolAddress((void**)&b1f, g_b1f);
    cudaGetSymbolAddress((void**)&ws1, g_ws1);      cudaGetSymbolAddress((void**)&bs1, g_bs1);
    cudaGetSymbolAddress((void**)&ws2, g_ws2);      cudaGetSymbolAddress((void**)&bs2, g_bs2);
    cudaGetSymbolAddress((void**)&ws3, g_ws3);      cudaGetSymbolAddress((void**)&bs3, g_bs3);
    cudaGetSymbolAddress((void**)&ws4, g_ws4);      cudaGetSymbolAddress((void**)&bs4, g_bs4);
    cudaGetSymbolAddress((void**)&ws5, g_ws5);      cudaGetSymbolAddress((void**)&bs5, g_bs5);
    cudaGetSymbolAddress((void**)&ws6, g_ws6);      cudaGetSymbolAddress((void**)&bs6, g_bs6);
    cudaGetSymbolAddress((void**)&ws7, g_ws7);      cudaGetSymbolAddress((void**)&bs7, g_bs7);
    cudaGetSymbolAddress((void**)&wqk, g_wqk);      cudaGetSymbolAddress((void**)&bqk, g_bqk);
    cudaGetSymbolAddress((void**)&wpv, g_wpv);

    const int SMEMSZ = SMEM_WORDS * 4;   // 46080 B
    cudaFuncSetAttribute(mma_gemm<0,false,__half>, cudaFuncAttributeMaxDynamicSharedMemorySize, SMEMSZ);
    cudaFuncSetAttribute(mma_gemm<0,false,float>,  cudaFuncAttributeMaxDynamicSharedMemorySize, SMEMSZ);
    cudaFuncSetAttribute(mma_gemm<1,false,__half>, cudaFuncAttributeMaxDynamicSharedMemorySize, SMEMSZ);
    cudaFuncSetAttribute(mma_gemm<1,true,__half>,  cudaFuncAttributeMaxDynamicSharedMemorySize, SMEMSZ);
    cudaFuncSetAttribute(mma_gemm<4,false,float>,  cudaFuncAttributeMaxDynamicSharedMemorySize, SMEMSZ);

    // ---- merged fold/convert ----
    FoldArgs fa;
    fa.w[0]=ca_w1; fa.bn[0]=ca_bn; fa.bin[0]=ca_b1; fa.wf[0]=nullptr; fa.bf[0]=b1f; fa.O[0]=MIPC; fa.Ke[0]=256;  fa.ro[0]=0;
    fa.w[1]=s1_w;  fa.bn[1]=s1_bn; fa.bin[1]=nullptr; fa.wf[1]=ws1; fa.bf[1]=bs1; fa.O[1]=CH; fa.Ke[1]=256;  fa.ro[1]=0;
    fa.w[2]=s2_w;  fa.bn[2]=s2_bn; fa.bin[2]=nullptr; fa.wf[2]=ws2; fa.bf[2]=bs2; fa.O[2]=CH; fa.Ke[2]=256;  fa.ro[2]=0;
    fa.w[3]=s3_w;  fa.bn[3]=s3_bn; fa.bin[3]=nullptr; fa.wf[3]=ws3; fa.bf[3]=bs3; fa.O[3]=CH; fa.Ke[3]=2304; fa.ro[3]=1;
    fa.w[4]=s4_w;  fa.bn[4]=s4_bn; fa.bin[4]=nullptr; fa.wf[4]=ws4; fa.bf[4]=bs4; fa.O[4]=CH; fa.Ke[4]=256;  fa.ro[4]=0;
    fa.w[5]=s5_w;  fa.bn[5]=s5_bn; fa.bin[5]=nullptr; fa.wf[5]=ws5; fa.bf[5]=bs5; fa.O[5]=CH; fa.Ke[5]=1024; fa.ro[5]=0;
    fa.w[6]=s6_w;  fa.bn[6]=s6_bn; fa.bin[6]=nullptr; fa.wf[6]=ws6; fa.bf[6]=bs6; fa.O[6]=CH; fa.Ke[6]=2304; fa.ro[6]=1;
    fa.w[7]=s7_w;  fa.bn[7]=s7_bn; fa.bin[7]=nullptr; fa.wf[7]=ws7; fa.bf[7]=bs7; fa.O[7]=CH; fa.Ke[7]=512;  fa.ro[7]=0;
    fa.w1f_f=w1f;
    fa.pq_w=pq_w; fa.pq_b=pq_b; fa.pk_w=pk_w; fa.pk_b=pk_b; fa.pv_w=pv_w;
    fa.qkw=wqk; fa.qkb=bqk; fa.pvw=wpv;
    fold_all_k<<<dim3(256,10),256>>>(fa);

    // ---- CoordAtt ----
    ca_pool_k<<<dim3(CH,BATCH),64>>>(x, pool);
    gemm_small_hsw<<<dim3(2,1,BATCH),256>>>(w1f, pool, b1f, yca,
        MIPC,128,CH, 128, (long)CH*128, (long)MIPC*128);
    ca_proj_k<<<dim3(64,2,BATCH),256>>>(ca_wh, ca_bh, ca_ww, ca_bw);
    ca_apply_k<<<dim3(128,8,BATCH),dim3(32,8)>>>(x);

    // ---- SPPCSPC ----
    mma_gemm<1,false,__half><<<dim3(2,64,BATCH),128,SMEMSZ>>>(r16, ws1, bs1, t1,
        256,256,256,256, 256,256,0, (long)CN,0,(long)CN);
    mma_gemm<1,true,__half><<<dim3(2,64,BATCH),128,SMEMSZ>>>(t1, ws3, bs3, t2,
        2304,256,2304,256, 256,256,0, (long)CN,0,(long)CN);
    mma_gemm<1,false,__half><<<dim3(2,64,BATCH),128,SMEMSZ>>>(t2, ws4, bs4, cat,
        256,256,256,1024, 256,256,0, (long)CN,0,(long)NPIX*1024);
    mp_all_k<<<dim3(128,BATCH),256>>>(cat);
    mma_gemm<1,false,__half><<<dim3(2,64,BATCH),128,SMEMSZ>>>(cat, ws5, bs5, t1,
        1024,1024,1024,256, 256,256,0, (long)NPIX*1024,0,(long)CN);
    mma_gemm<1,true,__half><<<dim3(2,64,BATCH),128,SMEMSZ>>>(t1, ws6, bs6, yc,
        2304,256,2304,512, 256,256,0, (long)CN,0,(long)NPIX*512);
    mma_gemm<1,false,__half><<<dim3(2,64,BATCH),128,SMEMSZ>>>(r16, ws2, bs2, yc+256,
        256,256,256,512, 256,256,0, (long)CN,0,(long)NPIX*512);
    mma_gemm<1,false,__half><<<dim3(2,64,BATCH),128,SMEMSZ>>>(yc, ws7, bs7, res16,
        512,512,512,256, 256,256,0, (long)NPIX*512,0,(long)CN, 1, res32);

    // ---- PAM ----
    mma_gemm<0,false,__half><<<dim3(1,64,BATCH),128,SMEMSZ>>>(res16, wqk, bqk, qk,
        256,256,256,64, 64,64,0, (long)CN,0,(long)NPIX*64);
    mma_gemm<0,false,__half><<<dim3(32,4,BATCH),128,SMEMSZ>>>(wpv, res16, pv_b, vb,
        256,256,256,NPIX, NPIX,NPIX,1, 0,(long)CN,(long)CN);
    mma_gemm<0,false,__half><<<dim3(32,64,BATCH),128,SMEMSZ>>>(qk, qk+32, nullptr, attn,
        CQD,64,64,NPIX, NPIX,NPIX,0, (long)NPIX*64,(long)NPIX*64,(long)NPIX*NPIX);
    softmax_row_k<<<BATCH*NPIX,256>>>(attn);
    mma_gemm<0,false,float><<<dim3(32,4,BATCH),128,SMEMSZ>>>(vb, attn, nullptr, pam,
        NPIX,NPIX,NPIX,NPIX, NPIX,NPIX,0, (long)CN,(long)NPIX*NPIX,(long)CN);

    // ---- CAM ----
    transpose_k<<<dim3(128,8,BATCH),dim3(32,8)>>>(res32);
    mma_gemm<0,false,float><<<dim3(2,4,BATCH*ESPLIT),128,SMEMSZ>>>(resT16, resT16, nullptr, epart,
        NPIX/ESPLIT,NPIX,NPIX,256, 256,256,0, (long)CN,(long)CN,(long)CH*CH, ESPLIT);
    cam_softmax_k<<<BATCH*CH,256>>>(epart, ac);
    mma_gemm<4,false,float><<<dim3(32,4,BATCH),128,SMEMSZ>>>(ac, res16, nullptr, (float*)d_out,
        256,256,256,NPIX, NPIX,NPIX,0, (long)CH*CH,(long)CN,(long)CN,
        1, nullptr, resT32, pam, gpa, gca);
}

// round 16
// speedup vs baseline: 1.1334x; 1.0384x over previous
#include <cuda_runtime.h>
#include <cuda_fp16.h>
#include <cstdint>

// Problem constants
#define BATCH 2
#define CH    256
#define NPIX  4096
#define MIPC  8
#define CQD   32
#define CN    (CH*NPIX)
#define ESPLIT 8

// ===================== static scratch ==================================
__device__ float  g_pool[BATCH*CH*128];
__device__ float  g_yca [BATCH*MIPC*128];
__device__ float  g_ah  [BATCH*CH*64];
__device__ float  g_aw  [BATCH*CH*64];
__device__ __half g_r   [BATCH*CN];              // NHWC half
__device__ __half g_t1  [BATCH*CN];
__device__ __half g_t2  [BATCH*CN];
__device__ __half g_cat [(long)BATCH*NPIX*1024];
__device__ __half g_mp  [BATCH*CN];
__device__ __half g_yc  [(long)BATCH*NPIX*512];
__device__ __half g_res16[BATCH*CN];             // NHWC half (operand)
__device__ float  g_res32[BATCH*CN];             // NHWC f32 (residual)
__device__ __half g_resT16[BATCH*CN];            // NCHW half (e GEMM)
__device__ float  g_resT32[BATCH*CN];            // NCHW f32 (final residual)
__device__ __half g_qk  [BATCH*NPIX*64];
__device__ __half g_v   [BATCH*CN];              // NCHW half
__device__ __half g_attn[(long)BATCH*NPIX*NPIX]; // 64 MB half
__device__ float  g_pam [BATCH*CN];              // NCHW f32
__device__ float  g_epart[BATCH*ESPLIT*CH*CH];
__device__ __half g_ac  [BATCH*CH*CH];
// folded weights (half) + biases (f32)
__device__ float  g_w1f[MIPC*CH];   __device__ float g_b1f[MIPC];
__device__ __half g_ws1[CH*CH];     __device__ float g_bs1[CH];
__device__ __half g_ws2[CH*CH];     __device__ float g_bs2[CH];
__device__ __half g_ws3[CH*2304];   __device__ float g_bs3[CH];
__device__ __half g_ws4[CH*CH];     __device__ float g_bs4[CH];
__device__ __half g_ws5[CH*1024];   __device__ float g_bs5[CH];
__device__ __half g_ws6[CH*2304];   __device__ float g_bs6[CH];
__device__ __half g_ws7[CH*512];    __device__ float g_bs7[CH];
__device__ __half g_wqk[64*CH];     __device__ float g_bqk[64];
__device__ __half g_wpv[CH*CH];

// ===================== merged fold/convert (1 launch) ==================
struct FoldArgs {
    const float* w[8]; const float* bn[8]; const float* bin[8];
    __half* wf[8]; float* bf[8];
    int O[8]; int Ke[8]; int ro[8];
    float* w1f_f;
    const float *pq_w, *pq_b, *pk_w, *pk_b, *pv_w;
    __half *qkw, *pvw;
    float *qkb;
};

__global__ void fold_all_k(FoldArgs a)
{
    __shared__ float s[2304];
    int j = blockIdx.y, o = blockIdx.x;
    if (j == 8) {
        if (o >= 64) return;
        const float* src = (o < 32) ? (a.pq_w + (long)o*256)
                                    : (a.pk_w + (long)(o-32)*256);
        for (int k = threadIdx.x; k < 256; k += blockDim.x)
            a.qkw[(long)o*256 + k] = __float2half(src[k]);
        if (threadIdx.x == 0)
            a.qkb[o] = (o < 32) ? a.pq_b[o] : a.pk_b[o-32];
        return;
    }
    if (j == 9) {
        for (int k = threadIdx.x; k < 256; k += blockDim.x)
            a.pvw[(long)o*256 + k] = __float2half(a.pv_w[(long)o*256 + k]);
        return;
    }
    int O = a.O[j];
    if (o >= O) return;
    const float* bn = a.bn[j];
    float g  = bn[o], be = bn[O+o], mn = bn[2*O+o], vr = bn[3*O+o];
    float s_ = g * rsqrtf(vr + 1e-5f);
    int Ke = a.Ke[j];
    const float* w = a.w[j];
    if (j == 0) {
        for (int k = threadIdx.x; k < Ke; k += blockDim.x)
            a.w1f_f[(long)o*Ke + k] = w[(long)o*Ke + k] * s_;
    } else if (a.ro[j]) {
        // coalesced read of src row, permuted via smem, coalesced write
        for (int idx = threadIdx.x; idx < 2304; idx += blockDim.x)
            s[idx] = w[(long)o*2304 + idx];          // src [o][ci][tap]
        __syncthreads();
        __half* wf = a.wf[j];
        for (int k = threadIdx.x; k < Ke; k += blockDim.x) {
            int t = k >> 8, ci = k & 255;            // dst [o][tap][ci]
            wf[(long)o*Ke + k] = __float2half(s[ci*9 + t] * s_);
        }
    } else {
        __half* wf = a.wf[j];
        for (int k = threadIdx.x; k < Ke; k += blockDim.x)
            wf[(long)o*Ke + k] = __float2half(w[(long)o*Ke + k] * s_);
    }
    if (threadIdx.x == 0)
        a.bf[j][o] = (a.bin[j] ? a.bin[j][o] : 0.f) * s_ + be - mn * s_;
}

// ===================== fp16 mma.sync primitives ========================
__device__ __forceinline__ void mma_f16(float c[4], const uint32_t a[4],
                                        const uint32_t b[2]) {
    asm volatile(
        "mma.sync.aligned.m16n8k16.row.col.f32.f16.f16.f32 "
        "{%0,%1,%2,%3}, {%4,%5,%6,%7}, {%8,%9}, {%0,%1,%2,%3};"
        : "+f"(c[0]), "+f"(c[1]), "+f"(c[2]), "+f"(c[3])
        : "r"(a[0]), "r"(a[1]), "r"(a[2]), "r"(a[3]), "r"(b[0]), "r"(b[1]));
}
__device__ __forceinline__ void ldsm4(uint32_t& r0, uint32_t& r1,
                                      uint32_t& r2, uint32_t& r3, uint32_t addr) {
    asm volatile("ldmatrix.sync.aligned.m8n8.x4.shared.b16 {%0,%1,%2,%3}, [%4];"
                 : "=r"(r0), "=r"(r1), "=r"(r2), "=r"(r3) : "r"(addr));
}
__device__ __forceinline__ void cp16(uint32_t dst, const void* src, int srcsize) {
    asm volatile("cp.async.cg.shared.global [%0], [%1], 16, %2;"
                 :: "r"(dst), "l"(src), "r"(srcsize));
}
#define CP_COMMIT() asm volatile("cp.async.commit_group;" ::: "memory")
#define CP_WAIT1()  asm volatile("cp.async.wait_group 1;" ::: "memory")

// SMEM rows: 32 halves data + 8 halves pad = 20 words
// Block tile 64(M) x 128(N): A stage 64 rows, B stage 128 rows
#define ROWW 20
#define ASTG (64*ROWW)           // 1280 words
#define BSTG (128*ROWW)          // 2560 words
#define STGW (ASTG+BSTG)         // 3840 words per stage
#define NSTG 3
#define SMEM_WORDS (NSTG*STGW)   // 11520 words = 46 KB

template<typename OutT>
__device__ __forceinline__ void st2(OutT* p, float v0, float v1);
template<> __device__ __forceinline__ void st2<__half>(__half* p, float v0, float v1) {
    *(__half2*)p = __floats2half2_rn(v0, v1);
}
template<> __device__ __forceinline__ void st2<float>(float* p, float v0, float v1) {
    *(float2*)p = make_float2(v0, v1);
}

// D[m0..+63][n0..+127] = act( sum_k A[m][k]*B[n][k] + bias )  (half in)
// ACT: 0 none, 1 SiLU (+opt f32 aux), 4 final combine
template<int ACT, bool CONV3, typename OutT>
__global__ __launch_bounds__(128) void mma_gemm(
    const __half* __restrict__ A, const __half* __restrict__ B,
    const float* __restrict__ bias, OutT* __restrict__ C,
    int K, int lda, int ldb, int ldc, int Bn, int ncols, int bias_on_m,
    long sA_, long sB_, long sC_,
    int nsplit = 1, float* __restrict__ Caux = nullptr,
    const float* __restrict__ f1 = nullptr, const float* __restrict__ f2 = nullptr,
    const float* __restrict__ gam1 = nullptr, const float* __restrict__ gam2 = nullptr)
{
    extern __shared__ uint32_t smu[];
    uint32_t sbase = (uint32_t)__cvta_generic_to_shared(smu);

    int bz = blockIdx.z;
    int batch = bz, slice = 0;
    if (nsplit > 1) { batch = bz / nsplit; slice = bz - batch * nsplit; }
    A += batch * sA_ + (long)slice * K;
    B += batch * sB_ + (long)slice * K;
    C += (long)bz * sC_;
    float gg1 = 0.f, gg2 = 0.f;
    if (ACT == 4) {
        f1 += (long)batch * CN; f2 += (long)batch * CN;
        gg1 = gam1[0]; gg2 = gam2[0];
    }

    int m0 = blockIdx.y * 64, n0 = blockIdx.x * 128;
    int tid = threadIdx.x;
    int lane = tid & 31, w = tid >> 5;
    int wm = w >> 1, wn = w & 1;           // 2x2 warp grid, 32x64 tiles
    int g = lane >> 2, t = lane & 3;

    float acc[2][8][4] = {};
    int lrow = tid >> 2, lv = tid & 3;
    int T = K >> 5;

    // ldmatrix lane address bases (bytes from sbase)
    uint32_t aAddr = sbase +
        (((wm*32 + (lane & 7) + ((lane >> 3) & 1)*8)*ROWW + ((lane >> 4) & 1)*4) << 2);
    uint32_t bAddr = sbase + (ASTG << 2) +
        (((wn*64 + (lane & 7) + ((lane >> 4) & 1)*8)*ROWW + ((lane >> 3) & 1)*4) << 2);

    auto issue = [&](int it) {
        int s = it % NSTG;
        int k0 = it * 32;
        uint32_t ab = sbase + (s*STGW)*4;
        uint32_t bb = ab + ASTG*4;
        if (!CONV3) {
            #pragma unroll
            for (int i = 0; i < 2; i++) {
                int m = i*32 + lrow;
                cp16(ab + ((m*ROWW + lv*4)*4),
                     A + (long)(m0+m)*lda + k0 + lv*8, 16);
            }
        } else {
            int tap = k0 >> 8, ci0 = k0 & 255;
            int dy = tap/3 - 1, dx = tap%3 - 1;
            #pragma unroll
            for (int i = 0; i < 2; i++) {
                int m = i*32 + lrow;
                int pix = m0 + m;
                int y = (pix >> 6) + dy, x = (pix & 63) + dx;
                bool ok = ((unsigned)y < 64u) && ((unsigned)x < 64u);
                const __half* src = ok ? (A + (long)((y<<6)+x)*lda + ci0 + lv*8) : A;
                cp16(ab + ((m*ROWW + lv*4)*4), src, ok ? 16 : 0);
            }
        }
        #pragma unroll
        for (int i = 0; i < 4; i++) {
            int n = i*32 + lrow;
            bool ok = (n0 + n) < Bn;
            const __half* src = ok ? (B + (long)(n0+n)*ldb + k0 + lv*8) : B;
            cp16(bb + ((n*ROWW + lv*4)*4), src, ok ? 16 : 0);
        }
        CP_COMMIT();
    };

    auto compute = [&](int s) {
        uint32_t soff = (uint32_t)(s*STGW) << 2;
        #pragma unroll
        for (int ks = 0; ks < 2; ks++) {
            uint32_t af[2][4], bf[8][2];
            #pragma unroll
            for (int mt = 0; mt < 2; mt++)
                ldsm4(af[mt][0], af[mt][1], af[mt][2], af[mt][3],
                      aAddr + soff + ((mt*16*ROWW + ks*8) << 2));
            #pragma unroll
            for (int p = 0; p < 4; p++) {
                uint32_t r0, r1, r2, r3;
                ldsm4(r0, r1, r2, r3,
                      bAddr + soff + ((p*16*ROWW + ks*8) << 2));
                bf[2*p][0]   = r0; bf[2*p][1]   = r1;
                bf[2*p+1][0] = r2; bf[2*p+1][1] = r3;
            }
            #pragma unroll
            for (int mt = 0; mt < 2; mt++)
                #pragma unroll
                for (int nt = 0; nt < 8; nt++)
                    mma_f16(acc[mt][nt], af[mt], bf[nt]);
        }
    };

    // prologue: 2 committed groups
    issue(0);
    if (T > 1) issue(1); else CP_COMMIT();

    for (int it = 0; it < T; it++) {
        CP_WAIT1();            // stage `it` landed
        __syncthreads();       // all warps done with slot being overwritten
        if (it + 2 < T) issue(it + 2); else CP_COMMIT();
        compute(it % NSTG);
    }

    // epilogue
    int valid = ncols - n0; if (valid > 128) valid = 128;
    #pragma unroll
    for (int mt = 0; mt < 2; mt++) {
        #pragma unroll
        for (int half_ = 0; half_ < 2; half_++) {
            int m = m0 + wm*32 + mt*16 + g + half_*8;
            float bm = (bias && bias_on_m) ? bias[m] : 0.f;
            long base = (long)m*ldc + n0;
            #pragma unroll
            for (int nt = 0; nt < 8; nt++) {
                int nl = wn*64 + nt*8 + 2*t;
                if (nl >= valid) continue;
                float v0 = acc[mt][nt][half_*2 + 0] + bm;
                float v1 = acc[mt][nt][half_*2 + 1] + bm;
                if (bias && !bias_on_m) { v0 += bias[n0+nl]; v1 += bias[n0+nl+1]; }
                if (ACT == 1) {
                    v0 = v0 / (1.f + __expf(-v0));
                    v1 = v1 / (1.f + __expf(-v1));
                    if (Caux) *(float2*)(Caux + (long)bz*sC_ + base + nl)
                              = make_float2(v0, v1);
                } else if (ACT == 4) {
                    float2 r1 = *(const float2*)(f1 + base + nl);
                    float2 r2 = *(const float2*)(f2 + base + nl);
                    v0 = 3.f*r1.x + gg1*r2.x + gg2*v0;
                    v1 = 3.f*r1.y + gg1*r2.y + gg2*v1;
                }
                st2<OutT>(C + base + nl, v0, v1);
            }
        }
    }
}

// ===================== small FMA GEMM (CoordAtt yca only) =============
__global__ __launch_bounds__(256) void gemm_small_hsw(
    const float* __restrict__ A, const float* __restrict__ B,
    const float* __restrict__ bias, float* __restrict__ C,
    int M, int N, int K, int ldb, long sB, long sC)
{
    int b = blockIdx.z;
    B += (long)b*sB; C += (long)b*sC;
    int m0 = blockIdx.y*64, n0 = blockIdx.x*64;
    __shared__ float As[16][64], Bs[16][65];
    int tid = threadIdx.x, tx = tid & 15, ty = tid >> 4;
    float acc[4][4] = {};
    for (int k0 = 0; k0 < K; k0 += 16) {
        int i = tid >> 2, jb = (tid & 3)*4, mI = m0 + i;
        #pragma unroll
        for (int j = 0; j < 4; j++) {
            int k = k0 + jb + j;
            As[jb+j][i] = (mI < M && k < K) ? A[(long)mI*K + k] : 0.f;
        }
        int jr = tid >> 4, nb = (tid & 15)*4, k = k0 + jr;
        #pragma unroll
        for (int n = 0; n < 4; n++) {
            int nn = n0 + nb + n;
            Bs[jr][nb+n] = (k < K && nn < N) ? B[(long)k*ldb + nn] : 0.f;
        }
        __syncthreads();
        #pragma unroll
        for (int j = 0; j < 16; j++) {
            float a[4], bb[4];
            #pragma unroll
            for (int i2 = 0; i2 < 4; i2++) a[i2]  = As[j][ty*4+i2];
            #pragma unroll
            for (int i2 = 0; i2 < 4; i2++) bb[i2] = Bs[j][tx*4+i2];
            #pragma unroll
            for (int i2 = 0; i2 < 4; i2++)
                #pragma unroll
                for (int jj = 0; jj < 4; jj++) acc[i2][jj] += a[i2]*bb[jj];
        }
        __syncthreads();
    }
    #pragma unroll
    for (int i = 0; i < 4; i++) {
        int mI = m0 + ty*4 + i;
        if (mI >= M) continue;
        float bv = bias ? bias[mI] : 0.f;
        #pragma unroll
        for (int jj = 0; jj < 4; jj++) {
            int n = n0 + tx*4 + jj;
            if (n >= N) continue;
            float v = acc[i][jj] + bv;
            float tq = fminf(fmaxf(v+3.f,0.f),6.f); v = v*tq*(1.f/6.f);  // h-swish
            C[(long)mI*N + n] = v;
        }
    }
}

// ===================== CoordAtt glue (coalesced) ======================
__global__ void ca_pool_k(const float* __restrict__ x, float* __restrict__ pool)
{
    __shared__ float s[64][65];
    int c = blockIdx.x, b = blockIdx.y, t = threadIdx.x;   // t < 64
    const float* p = x + ((long)b*CH + c)*NPIX;
    for (int i = 0; i < 64; i++) s[i][t] = p[i*64 + t];    // coalesced
    __syncthreads();
    float sh = 0.f, sw = 0.f;
    for (int i = 0; i < 64; i++) { sh += s[t][i]; sw += s[i][t]; }
    float* o = pool + ((long)b*CH + c)*128;
    o[t] = sh*(1.f/64.f); o[64+t] = sw*(1.f/64.f);
}

__global__ void ca_proj_k(const float* __restrict__ wh, const float* __restrict__ bh,
                          const float* __restrict__ ww, const float* __restrict__ bw)
{
    int hw = blockIdx.y, b = blockIdx.z;
    int idx = blockIdx.x*256 + threadIdx.x;
    int c = idx >> 6, pos = idx & 63;
    const float* W  = hw ? ww : wh;
    const float* Bi = hw ? bw : bh;
    const float* y  = g_yca + (long)b*MIPC*128 + (hw ? 64 : 0) + pos;
    float s = Bi[c];
    #pragma unroll
    for (int i = 0; i < MIPC; i++) s += W[c*MIPC + i] * y[i*128];
    float o = 1.f / (1.f + __expf(-s));
    float* dst = hw ? g_aw : g_ah;
    dst[((long)b*CH + c)*64 + pos] = o;
}

// tiled NCHW->NHWC apply: coalesced reads along pix, coalesced writes along c
__global__ void ca_apply_k(const float* __restrict__ x)
{
    __shared__ float s[32][33];
    int b = blockIdx.z;
    int p0 = blockIdx.x*32, c0 = blockIdx.y*32;
    int tx = threadIdx.x, ty = threadIdx.y;   // 32 x 8
    const float* X = x + (long)b*CN;
    __half* R = g_r + (long)b*CN;
    #pragma unroll
    for (int j = 0; j < 32; j += 8)
        s[ty+j][tx] = X[(long)(c0+ty+j)*4096 + p0+tx];
    __syncthreads();
    #pragma unroll
    for (int j = 0; j < 32; j += 8) {
        int pix = p0 + ty + j;
        int c = c0 + tx;
        long bc = (long)b*CH + c;
        float v = s[tx][ty+j] * g_aw[bc*64 + (pix & 63)] * g_ah[bc*64 + (pix >> 6)];
        R[(long)pix*256 + c] = __float2half(v);
    }
}

// ===================== separated coalesced maxpool (5-wide) ============
__global__ void mp_h_k(const __half* __restrict__ src, __half* __restrict__ tmp)
{
    long i = blockIdx.x*256L + threadIdx.x;       // BATCH*NPIX*128 half2
    if (i >= (long)BATCH*NPIX*128) return;
    int c2 = (int)(i & 127); long t = i >> 7;
    int pix = (int)(t & 4095); int b = (int)(t >> 12);
    int y = pix >> 6, x = pix & 63;
    const __half2* s = (const __half2*)(src + (long)b*NPIX*1024);
    __half2 m = __float2half2_rn(-65504.f);
    #pragma unroll
    for (int d = -2; d <= 2; d++) {
        int xx = x + d;
        if ((unsigned)xx < 64u) m = __hmax2(m, s[(long)((y<<6)+xx)*512 + c2]);
    }
    ((__half2*)(tmp + (long)b*CN))[(long)pix*128 + c2] = m;
}
__global__ void mp_v_k(const __half* __restrict__ tmp, __half* __restrict__ dst)
{
    long i = blockIdx.x*256L + threadIdx.x;
    if (i >= (long)BATCH*NPIX*128) return;
    int c2 = (int)(i & 127); long t = i >> 7;
    int pix = (int)(t & 4095); int b = (int)(t >> 12);
    int y = pix >> 6, x = pix & 63;
    const __half2* s = (const __half2*)(tmp + (long)b*CN);
    __half2 m = __float2half2_rn(-65504.f);
    #pragma unroll
    for (int d = -2; d <= 2; d++) {
        int yy = y + d;
        if ((unsigned)yy < 64u) m = __hmax2(m, s[(long)((yy<<6)+x)*128 + c2]);
    }
    ((__half2*)(dst + (long)b*NPIX*1024))[(long)pix*512 + c2] = m;
}

// ===================== PAM softmax (half rows of 4096) =================
__global__ void softmax_row_k(__half* __restrict__ a)
{
    __half2* p = (__half2*)(a + (long)blockIdx.x * 4096);
    int t = threadIdx.x;
    __shared__ float red[256];
    float2 v[8];
    #pragma unroll
    for (int i = 0; i < 8; i++) v[i] = __half22float2(p[t + i*256]);
    float mx = v[0].x;
    #pragma unroll
    for (int i = 0; i < 8; i++) { mx = fmaxf(mx, v[i].x); mx = fmaxf(mx, v[i].y); }
    red[t] = mx; __syncthreads();
    for (int s = 128; s > 0; s >>= 1) { if (t < s) red[t] = fmaxf(red[t], red[t+s]); __syncthreads(); }
    mx = red[0]; __syncthreads();
    float sum = 0.f;
    #pragma unroll
    for (int i = 0; i < 8; i++) {
        v[i].x = __expf(v[i].x - mx); v[i].y = __expf(v[i].y - mx);
        sum += v[i].x + v[i].y;
    }
    red[t] = sum; __syncthreads();
    for (int s = 128; s > 0; s >>= 1) { if (t < s) red[t] += red[t+s]; __syncthreads(); }
    float inv = 1.f / red[0];
    #pragma unroll
    for (int i = 0; i < 8; i++)
        p[t + i*256] = __floats2half2_rn(v[i].x * inv, v[i].y * inv);
}

// ====== CAM softmax fused with split-K reduce ==========================
__global__ void cam_softmax_k(const float* __restrict__ ep, __half* __restrict__ ac)
{
    long row = blockIdx.x;           // b*256 + c
    int b = (int)(row >> 8); int r = (int)(row & 255);
    int t = threadIdx.x;
    float v = 0.f;
    #pragma unroll
    for (int k = 0; k < ESPLIT; k++)
        v += ep[((long)(b*ESPLIT + k) << 16) + r*256 + t];
    __shared__ float sm[256];
    sm[t] = v; __syncthreads();
    for (int s = 128; s > 0; s >>= 1) { if (t < s) sm[t] = fmaxf(sm[t], sm[t+s]); __syncthreads(); }
    float rowmax = sm[0]; __syncthreads();
    float z = rowmax - v;
    sm[t] = z; __syncthreads();
    for (int s = 128; s > 0; s >>= 1) { if (t < s) sm[t] = fmaxf(sm[t], sm[t+s]); __syncthreads(); }
    float zm = sm[0]; __syncthreads();
    float pe = __expf(z - zm);
    sm[t] = pe; __syncthreads();
    for (int s = 128; s > 0; s >>= 1) { if (t < s) sm[t] += sm[t+s]; __syncthreads(); }
    ac[row*256 + t] = __float2half(pe / sm[0]);
}

// ============ tiled transpose NHWC(f32) -> NCHW f32 + half =============
__global__ void transpose_k(const float* __restrict__ src)
{
    __shared__ float s[32][33];
    int b = blockIdx.z;
    int p0 = blockIdx.x*32, c0 = blockIdx.y*32;
    int tx = threadIdx.x, ty = threadIdx.y;  // 32 x 8
    const float* S = src + (long)b*CN;
    float*  D32 = g_resT32 + (long)b*CN;
    __half* D16 = g_resT16 + (long)b*CN;
    #pragma unroll
    for (int j = 0; j < 32; j += 8)
        s[ty+j][tx] = S[(long)(p0+ty+j)*256 + c0+tx];
    __syncthreads();
    #pragma unroll
    for (int j = 0; j < 32; j += 8) {
        float v = s[tx][ty+j];
        long o = (long)(c0+ty+j)*4096 + p0+tx;
        D32[o] = v;
        D16[o] = __float2half(v);
    }
}

// ======================================================================
extern "C" void kernel_launch(void* const* d_in, const int* in_sizes, int n_in,
                              void* d_out, int out_size)
{
    const float* x     = (const float*)d_in[0];
    const float* ca_w1 = (const float*)d_in[1];
    const float* ca_b1 = (const float*)d_in[2];
    const float* ca_bn = (const float*)d_in[3];
    const float* ca_wh = (const float*)d_in[4];
    const float* ca_bh = (const float*)d_in[5];
    const float* ca_ww = (const float*)d_in[6];
    const float* ca_bw = (const float*)d_in[7];
    const float* s1_w  = (const float*)d_in[8];  const float* s1_bn = (const float*)d_in[9];
    const float* s2_w  = (const float*)d_in[10]; const float* s2_bn = (const float*)d_in[11];
    const float* s3_w  = (const float*)d_in[12]; const float* s3_bn = (const float*)d_in[13];
    const float* s4_w  = (const float*)d_in[14]; const float* s4_bn = (const float*)d_in[15];
    const float* s5_w  = (const float*)d_in[16]; const float* s5_bn = (const float*)d_in[17];
    const float* s6_w  = (const float*)d_in[18]; const float* s6_bn = (const float*)d_in[19];
    const float* s7_w  = (const float*)d_in[20]; const float* s7_bn = (const float*)d_in[21];
    const float* pq_w  = (const float*)d_in[22]; const float* pq_b  = (const float*)d_in[23];
    const float* pk_w  = (const float*)d_in[24]; const float* pk_b  = (const float*)d_in[25];
    const float* pv_w  = (const float*)d_in[26]; const float* pv_b  = (const float*)d_in[27];
    const float* gpa   = (const float*)d_in[28];
    const float* gca   = (const float*)d_in[29];

    float *pool,*yca,*res32,*pam,*epart,*w1f,*b1f,*bs1,*bs2,*bs3,*bs4,*bs5,*bs6,*bs7,*bqk;
    __half *r16,*t1,*t2,*cat,*mp,*yc,*res16,*resT16,*qk,*vb,*attn,*ac;
    __half *ws1,*ws2,*ws3,*ws4,*ws5,*ws6,*ws7,*wqk,*wpv;
    float *resT32;
    cudaGetSymbolAddress((void**)&pool, g_pool);    cudaGetSymbolAddress((void**)&yca, g_yca);
    cudaGetSymbolAddress((void**)&r16, g_r);        cudaGetSymbolAddress((void**)&t1, g_t1);
    cudaGetSymbolAddress((void**)&t2, g_t2);        cudaGetSymbolAddress((void**)&cat, g_cat);
    cudaGetSymbolAddress((void**)&mp, g_mp);        cudaGetSymbolAddress((void**)&yc, g_yc);
    cudaGetSymbolAddress((void**)&res16, g_res16);  cudaGetSymbolAddress((void**)&res32, g_res32);
    cudaGetSymbolAddress((void**)&resT16, g_resT16);cudaGetSymbolAddress((void**)&resT32, g_resT32);
    cudaGetSymbolAddress((void**)&qk, g_qk);        cudaGetSymbolAddress((void**)&vb, g_v);
    cudaGetSymbolAddress((void**)&attn, g_attn);    cudaGetSymbolAddress((void**)&pam, g_pam);
    cudaGetSymbolAddress((void**)&epart, g_epart);  cudaGetSymbolAddress((void**)&ac, g_ac);
    cudaGetSymbolAddress((void**)&w1f, g_w1f);      cudaGetSymbolAddress((void**)&b1f, g_b1f);
    cudaGetSymbolAddress((void**)&ws1, g_ws1);      cudaGetSymbolAddress((void**)&bs1, g_bs1);
    cudaGetSymbolAddress((void**)&ws2, g_ws2);      cudaGetSymbolAddress((void**)&bs2, g_bs2);
    cudaGetSymbolAddress((void**)&ws3, g_ws3);      cudaGetSymbolAddress((void**)&bs3, g_bs3);
    cudaGetSymbolAddress((void**)&ws4, g_ws4);      cudaGetSymbolAddress((void**)&bs4, g_bs4);
    cudaGetSymbolAddress((void**)&ws5, g_ws5);      cudaGetSymbolAddress((void**)&bs5, g_bs5);
    cudaGetSymbolAddress((void**)&ws6, g_ws6);      cudaGetSymbolAddress((void**)&bs6, g_bs6);
    cudaGetSymbolAddress((void**)&ws7, g_ws7);      cudaGetSymbolAddress((void**)&bs7, g_bs7);
    cudaGetSymbolAddress((void**)&wqk, g_wqk);      cudaGetSymbolAddress((void**)&bqk, g_bqk);
    cudaGetSymbolAddress((void**)&wpv, g_wpv);

    const int SMEMSZ = SMEM_WORDS * 4;   // 46080 B
    cudaFuncSetAttribute(mma_gemm<0,false,__half>, cudaFuncAttributeMaxDynamicSharedMemorySize, SMEMSZ);
    cudaFuncSetAttribute(mma_gemm<0,false,float>,  cudaFuncAttributeMaxDynamicSharedMemorySize, SMEMSZ);
    cudaFuncSetAttribute(mma_gemm<1,false,__half>, cudaFuncAttributeMaxDynamicSharedMemorySize, SMEMSZ);
    cudaFuncSetAttribute(mma_gemm<1,true,__half>,  cudaFuncAttributeMaxDynamicSharedMemorySize, SMEMSZ);
    cudaFuncSetAttribute(mma_gemm<4,false,float>,  cudaFuncAttributeMaxDynamicSharedMemorySize, SMEMSZ);

    const int EB2 = (int)(((long)BATCH*NPIX*128 + 255)/256);

    // ---- merged fold/convert ----
    FoldArgs fa;
    fa.w[0]=ca_w1; fa.bn[0]=ca_bn; fa.bin[0]=ca_b1; fa.wf[0]=nullptr; fa.bf[0]=b1f; fa.O[0]=MIPC; fa.Ke[0]=256;  fa.ro[0]=0;
    fa.w[1]=s1_w;  fa.bn[1]=s1_bn; fa.bin[1]=nullptr; fa.wf[1]=ws1; fa.bf[1]=bs1; fa.O[1]=CH; fa.Ke[1]=256;  fa.ro[1]=0;
    fa.w[2]=s2_w;  fa.bn[2]=s2_bn; fa.bin[2]=nullptr; fa.wf[2]=ws2; fa.bf[2]=bs2; fa.O[2]=CH; fa.Ke[2]=256;  fa.ro[2]=0;
    fa.w[3]=s3_w;  fa.bn[3]=s3_bn; fa.bin[3]=nullptr; fa.wf[3]=ws3; fa.bf[3]=bs3; fa.O[3]=CH; fa.Ke[3]=2304; fa.ro[3]=1;
    fa.w[4]=s4_w;  fa.bn[4]=s4_bn; fa.bin[4]=nullptr; fa.wf[4]=ws4; fa.bf[4]=bs4; fa.O[4]=CH; fa.Ke[4]=256;  fa.ro[4]=0;
    fa.w[5]=s5_w;  fa.bn[5]=s5_bn; fa.bin[5]=nullptr; fa.wf[5]=ws5; fa.bf[5]=bs5; fa.O[5]=CH; fa.Ke[5]=1024; fa.ro[5]=0;
    fa.w[6]=s6_w;  fa.bn[6]=s6_bn; fa.bin[6]=nullptr; fa.wf[6]=ws6; fa.bf[6]=bs6; fa.O[6]=CH; fa.Ke[6]=2304; fa.ro[6]=1;
    fa.w[7]=s7_w;  fa.bn[7]=s7_bn; fa.bin[7]=nullptr; fa.wf[7]=ws7; fa.bf[7]=bs7; fa.O[7]=CH; fa.Ke[7]=512;  fa.ro[7]=0;
    fa.w1f_f=w1f;
    fa.pq_w=pq_w; fa.pq_b=pq_b; fa.pk_w=pk_w; fa.pk_b=pk_b; fa.pv_w=pv_w;
    fa.qkw=wqk; fa.qkb=bqk; fa.pvw=wpv;
    fold_all_k<<<dim3(256,10),256>>>(fa);

    // ---- CoordAtt ----
    ca_pool_k<<<dim3(CH,BATCH),64>>>(x, pool);
    gemm_small_hsw<<<dim3(2,1,BATCH),256>>>(w1f, pool, b1f, yca,
        MIPC,128,CH, 128, (long)CH*128, (long)MIPC*128);
    ca_proj_k<<<dim3(64,2,BATCH),256>>>(ca_wh, ca_bh, ca_ww, ca_bw);
    ca_apply_k<<<dim3(128,8,BATCH),dim3(32,8)>>>(x);

    // ---- SPPCSPC ----
    mma_gemm<1,false,__half><<<dim3(2,64,BATCH),128,SMEMSZ>>>(r16, ws1, bs1, t1,
        256,256,256,256, 256,256,0, (long)CN,0,(long)CN);
    mma_gemm<1,true,__half><<<dim3(2,64,BATCH),128,SMEMSZ>>>(t1, ws3, bs3, t2,
        2304,256,2304,256, 256,256,0, (long)CN,0,(long)CN);
    mma_gemm<1,false,__half><<<dim3(2,64,BATCH),128,SMEMSZ>>>(t2, ws4, bs4, cat,
        256,256,256,1024, 256,256,0, (long)CN,0,(long)NPIX*1024);
    mp_h_k<<<EB2,256>>>(cat,       mp); mp_v_k<<<EB2,256>>>(mp, cat+256);
    mp_h_k<<<EB2,256>>>(cat+256,   mp); mp_v_k<<<EB2,256>>>(mp, cat+512);
    mp_h_k<<<EB2,256>>>(cat+512,   mp); mp_v_k<<<EB2,256>>>(mp, cat+768);
    mma_gemm<1,false,__half><<<dim3(2,64,BATCH),128,SMEMSZ>>>(cat, ws5, bs5, t1,
        1024,1024,1024,256, 256,256,0, (long)NPIX*1024,0,(long)CN);
    mma_gemm<1,true,__half><<<dim3(2,64,BATCH),128,SMEMSZ>>>(t1, ws6, bs6, yc,
        2304,256,2304,512, 256,256,0, (long)CN,0,(long)NPIX*512);
    mma_gemm<1,false,__half><<<dim3(2,64,BATCH),128,SMEMSZ>>>(r16, ws2, bs2, yc+256,
        256,256,256,512, 256,256,0, (long)CN,0,(long)NPIX*512);
    mma_gemm<1,false,__half><<<dim3(2,64,BATCH),128,SMEMSZ>>>(yc, ws7, bs7, res16,
        512,512,512,256, 256,256,0, (long)NPIX*512,0,(long)CN, 1, res32);

    // ---- PAM ----
    mma_gemm<0,false,__half><<<dim3(1,64,BATCH),128,SMEMSZ>>>(res16, wqk, bqk, qk,
        256,256,256,64, 64,64,0, (long)CN,0,(long)NPIX*64);
    mma_gemm<0,false,__half><<<dim3(32,4,BATCH),128,SMEMSZ>>>(wpv, res16, pv_b, vb,
        256,256,256,NPIX, NPIX,NPIX,1, 0,(long)CN,(long)CN);
    mma_gemm<0,false,__half><<<dim3(32,64,BATCH),128,SMEMSZ>>>(qk, qk+32, nullptr, attn,
        CQD,64,64,NPIX, NPIX,NPIX,0, (long)NPIX*64,(long)NPIX*64,(long)NPIX*NPIX);
    softmax_row_k<<<BATCH*NPIX,256>>>(attn);
    mma_gemm<0,false,float><<<dim3(32,4,BATCH),128,SMEMSZ>>>(vb, attn, nullptr, pam,
        NPIX,NPIX,NPIX,NPIX, NPIX,NPIX,0, (long)CN,(long)NPIX*NPIX,(long)CN);

    // ---- CAM ----
    transpose_k<<<dim3(128,8,BATCH),dim3(32,8)>>>(res32);
    mma_gemm<0,false,float><<<dim3(2,4,BATCH*ESPLIT),128,SMEMSZ>>>(resT16, resT16, nullptr, epart,
        NPIX/ESPLIT,NPIX,NPIX,256, 256,256,0, (long)CN,(long)CN,(long)CH*CH, ESPLIT);
    cam_softmax_k<<<BATCH*CH,256>>>(epart, ac);
    mma_gemm<4,false,float><<<dim3(32,4,BATCH),128,SMEMSZ>>>(ac, res16, nullptr, (float*)d_out,
        256,256,256,NPIX, NPIX,NPIX,0, (long)CH*CH,(long)CN,(long)CN,
        1, nullptr, resT32, pam, gpa, gca);
}